// round 6
// baseline (speedup 1.0000x reference)
#include <cuda_runtime.h>
#include <cuda_bf16.h>
#include <math.h>
#include <stdint.h>

#define SEQ     4096
#define DMODEL  2048
#define DHEAD   128
#define NH      16
#define NKV     4
#define NCOLS   3072
#define KDIM    2048

// ---------------- scratch ----------------
__device__ __align__(256) float g_bcat[NCOLS];
__device__ __align__(256) __nv_bfloat16 g_xhi[SEQ * DMODEL];
__device__ __align__(256) __nv_bfloat16 g_xlo[SEQ * DMODEL];
__device__ __align__(256) __nv_bfloat16 g_zhi[SEQ * DMODEL];
__device__ __align__(256) __nv_bfloat16 g_zlo[SEQ * DMODEL];
__device__ __align__(256) __nv_bfloat16 g_Wthi[NCOLS * KDIM];
__device__ __align__(256) __nv_bfloat16 g_Wtlo[NCOLS * KDIM];
__device__ __align__(256) __nv_bfloat16 g_WOthi[DMODEL * KDIM];
__device__ __align__(256) __nv_bfloat16 g_WOtlo[DMODEL * KDIM];
__device__ __align__(256) __nv_bfloat16 g_qbhi[SEQ * DMODEL];
__device__ __align__(256) __nv_bfloat16 g_qblo[SEQ * DMODEL];
__device__ __align__(256) __nv_bfloat16 g_kbhi[NKV * SEQ * DHEAD];
__device__ __align__(256) __nv_bfloat16 g_kblo[NKV * SEQ * DHEAD];
__device__ __align__(256) __nv_bfloat16 g_vthi[NKV * DHEAD * SEQ];
__device__ __align__(256) __nv_bfloat16 g_vtlo[NKV * DHEAD * SEQ];
__device__ __align__(256) float g_rcos[SEQ * 64];
__device__ __align__(256) float g_rsin[SEQ * 64];

// ---------------- helpers ----------------
__device__ __forceinline__ uint32_t smem_u32(const void* p) {
    uint32_t a;
    asm("{ .reg .u64 t; cvta.to.shared.u64 t, %1; cvt.u32.u64 %0, t; }" : "=r"(a) : "l"(p));
    return a;
}
__device__ __forceinline__ void cp16(uint32_t s, const void* g) {
    asm volatile("cp.async.cg.shared.global [%0], [%1], 16;" :: "r"(s), "l"(g));
}
#define CP_COMMIT() asm volatile("cp.async.commit_group;" ::: "memory")
__device__ __forceinline__ void ldsm4(uint32_t* r, uint32_t addr) {
    asm volatile("ldmatrix.sync.aligned.m8n8.x4.shared.b16 {%0,%1,%2,%3}, [%4];"
        : "=r"(r[0]), "=r"(r[1]), "=r"(r[2]), "=r"(r[3]) : "r"(addr));
}
__device__ __forceinline__ void mma_bf16(float* d, const uint32_t* a, const uint32_t* b) {
    asm volatile("mma.sync.aligned.m16n8k16.row.col.f32.bf16.bf16.f32 "
        "{%0,%1,%2,%3}, {%4,%5,%6,%7}, {%8,%9}, {%0,%1,%2,%3};"
        : "+f"(d[0]), "+f"(d[1]), "+f"(d[2]), "+f"(d[3])
        : "r"(a[0]), "r"(a[1]), "r"(a[2]), "r"(a[3]), "r"(b[0]), "r"(b[1]));
}
__device__ __forceinline__ float ex2f(float x) {
    float y; asm("ex2.approx.ftz.f32 %0, %1;" : "=f"(y) : "f"(x)); return y;
}
__device__ __forceinline__ void split2(float p0, float p1, uint32_t& hi, uint32_t& lo) {
    __nv_bfloat16 h0 = __float2bfloat16(p0), h1 = __float2bfloat16(p1);
    float r0 = p0 - __bfloat162float(h0), r1 = p1 - __bfloat162float(h1);
    __nv_bfloat16 e0 = __float2bfloat16(r0), e1 = __float2bfloat16(r1);
    hi = ((uint32_t)__bfloat16_as_ushort(h1) << 16) | (uint32_t)__bfloat16_as_ushort(h0);
    lo = ((uint32_t)__bfloat16_as_ushort(e1) << 16) | (uint32_t)__bfloat16_as_ushort(e0);
}
__device__ __forceinline__ void split1(float v, __nv_bfloat16& h, __nv_bfloat16& l) {
    h = __float2bfloat16(v);
    l = __float2bfloat16(v - __bfloat162float(h));
}
__device__ __forceinline__ void store_pair(__nv_bfloat16* hi, __nv_bfloat16* lo,
                                           size_t off, float v0, float v1) {
    __nv_bfloat16 h0, l0, h1, l1;
    split1(v0, h0, l0);
    split1(v1, h1, l1);
    *(__nv_bfloat162*)(hi + off) = __nv_bfloat162(h0, h1);
    *(__nv_bfloat162*)(lo + off) = __nv_bfloat162(l0, l1);
}
#define SWZ(off) ((off) ^ (((off) >> 3) & 0x70))

// ---------------- repack QKV weights + bias + rotary table (merged) ----------------
#define REP_BLOCKS ((NCOLS * KDIM) / 256)
__global__ void repack_wqkv_rot(const float* __restrict__ WQ, const float* __restrict__ WK,
                                const float* __restrict__ WV, const float* __restrict__ bQ,
                                const float* __restrict__ bK, const float* __restrict__ bV) {
    if (blockIdx.x >= REP_BLOCKS) {
        int idx = (blockIdx.x - REP_BLOCKS) * 256 + threadIdx.x;
        if (idx >= SEQ * 64) return;
        int j = idx & 63, s = idx >> 6;
        double dfreq = pow(10000.0, -(double)j / 64.0);
        float freq = (float)dfreq;
        float angle = (float)s * freq;
        double da = (double)angle;
        g_rcos[idx] = (float)cos(da);
        g_rsin[idx] = (float)sin(da);
        return;
    }
    int idx = blockIdx.x * 256 + threadIdx.x;
    if (idx < NCOLS) {
        float b;
        if      (idx < 2048) b = bQ[idx];
        else if (idx < 2560) b = bK[idx - 2048];
        else                 b = bV[idx - 2560];
        g_bcat[idx] = b;
    }
    int n = idx >> 11;
    int k = idx & 2047;
    float v;
    if (n < 2048) {
        int head = n >> 7, h = n & 127;
        v = WQ[((size_t)head * KDIM + k) * DHEAD + h];
    } else if (n < 2560) {
        int head = (n - 2048) >> 7, h = n & 127;
        v = WK[((size_t)head * KDIM + k) * DHEAD + h];
    } else {
        int head = (n - 2560) >> 7, h = n & 127;
        v = WV[((size_t)head * KDIM + k) * DHEAD + h];
    }
    __nv_bfloat16 hi, lo;
    split1(v, hi, lo);
    g_Wthi[idx] = hi;
    g_Wtlo[idx] = lo;
}

__global__ void repack_wo(const float* __restrict__ WO) {
    int idx = blockIdx.x * blockDim.x + threadIdx.x;
    if (idx >= DMODEL * KDIM) return;
    int k = idx >> 11;
    int m = idx & 2047;
    __nv_bfloat16 hi, lo;
    split1(WO[idx], hi, lo);
    g_WOthi[(size_t)m * KDIM + k] = hi;
    g_WOtlo[(size_t)m * KDIM + k] = lo;
}

__global__ void split_f32(const float* __restrict__ src, __nv_bfloat16* __restrict__ hi,
                          __nv_bfloat16* __restrict__ lo, int n) {
    int i = blockIdx.x * blockDim.x + threadIdx.x;
    if (i >= n) return;
    __nv_bfloat16 h, l;
    split1(src[i], h, l);
    hi[i] = h;
    lo[i] = l;
}

// ---------------- 512-thread mma.sync bf16x3 GEMM, 2-stage ----------------
// 16 warps, warp grid 4(m) x 4(n), warp tile 32x32.
// EPI=0: C = A*B^T + bias. EPI=1: fused QKV epilogue (rotary + splits + layouts).
#define BM 128
#define BN 128
#define BKT 64
#define MATB 16384
#define BUFB (4 * MATB)        // 64 KB per stage
#define GSMEM (2 * BUFB)       // 128 KB
#define NSTG (KDIM / BKT)      // 32

__device__ __forceinline__ void load_stage(uint32_t bb, int k0, int m0, int n0, int tid,
                                           const __nv_bfloat16* Ahi, const __nv_bfloat16* Alo,
                                           const __nv_bfloat16* Bhi, const __nv_bfloat16* Blo) {
    #pragma unroll
    for (int i = 0; i < 2; i++) {
        int c = tid + i * 512;        // 0..1023
        int r = c >> 3, ch = c & 7;
        uint32_t so = bb + SWZ(r * 128 + ch * 16);
        size_t ga = (size_t)(m0 + r) * KDIM + k0 + ch * 8;
        size_t gb = (size_t)(n0 + r) * KDIM + k0 + ch * 8;
        cp16(so,            Ahi + ga);
        cp16(so + MATB,     Alo + ga);
        cp16(so + 2 * MATB, Bhi + gb);
        cp16(so + 3 * MATB, Blo + gb);
    }
}

template<int EPI>
__global__ __launch_bounds__(512, 1) void gemm3(
    const __nv_bfloat16* __restrict__ Ahi, const __nv_bfloat16* __restrict__ Alo,
    const __nv_bfloat16* __restrict__ Bhi, const __nv_bfloat16* __restrict__ Blo,
    const float* __restrict__ bias, float* __restrict__ C, int N)
{
    extern __shared__ char sm[];
    const uint32_t smb = smem_u32(sm);
    const int tid = threadIdx.x;
    const int wid = tid >> 5, lid = tid & 31;
    const int m0 = blockIdx.x * BM, n0 = blockIdx.y * BN;
    const int wm = (wid & 3) * 32;
    const int wn = (wid >> 2) * 32;

    float acc[2][4][4];
    #pragma unroll
    for (int i = 0; i < 2; i++)
        #pragma unroll
        for (int j = 0; j < 4; j++)
            #pragma unroll
            for (int k = 0; k < 4; k++) acc[i][j][k] = 0.f;

    const int arow = lid & 15;
    const int asel = (lid >> 4) * 16;
    const int brow = ((lid >> 4) << 3) + (lid & 7);
    const int bsel = ((lid >> 3) & 1) * 16;

    load_stage(smb, 0, m0, n0, tid, Ahi, Alo, Bhi, Blo);
    CP_COMMIT();

    for (int s = 0; s < NSTG; s++) {
        if (s + 1 < NSTG) {
            load_stage(smb + ((s + 1) & 1) * BUFB, (s + 1) * BKT, m0, n0, tid,
                       Ahi, Alo, Bhi, Blo);
            CP_COMMIT();
            asm volatile("cp.async.wait_group 1;" ::: "memory");
        } else {
            asm volatile("cp.async.wait_group 0;" ::: "memory");
        }
        __syncthreads();

        uint32_t bb = smb + (s & 1) * BUFB;
        #pragma unroll
        for (int kk = 0; kk < 4; kk++) {
            uint32_t ah[2][4], al[2][4];
            #pragma unroll
            for (int ms = 0; ms < 2; ms++) {
                uint32_t off = SWZ((wm + ms * 16 + arow) * 128 + kk * 32 + asel);
                ldsm4(ah[ms], bb + off);
                ldsm4(al[ms], bb + MATB + off);
            }
            uint32_t bh[2][4], bl[2][4];
            #pragma unroll
            for (int ns = 0; ns < 2; ns++) {
                uint32_t off = SWZ((wn + ns * 16 + brow) * 128 + kk * 32 + bsel);
                ldsm4(bh[ns], bb + 2 * MATB + off);
                ldsm4(bl[ns], bb + 3 * MATB + off);
            }
            #pragma unroll
            for (int ms = 0; ms < 2; ms++)
                #pragma unroll
                for (int n8 = 0; n8 < 4; n8++) {
                    const uint32_t* ph = &bh[n8 >> 1][(n8 & 1) * 2];
                    const uint32_t* pl = &bl[n8 >> 1][(n8 & 1) * 2];
                    mma_bf16(acc[ms][n8], ah[ms], ph);
                    mma_bf16(acc[ms][n8], ah[ms], pl);
                    mma_bf16(acc[ms][n8], al[ms], ph);
                }
        }
        __syncthreads();
    }

    const int erow = lid >> 2, ecol = (lid & 3) * 2;
    #pragma unroll
    for (int ms = 0; ms < 2; ms++) {
        int r0 = m0 + wm + ms * 16 + erow;
        #pragma unroll
        for (int n8 = 0; n8 < 4; n8++) {
            int c = n0 + wn + n8 * 8 + ecol;
            float2 bv = *(const float2*)&bias[c];
            float a00 = acc[ms][n8][0] + bv.x, a01 = acc[ms][n8][1] + bv.y;
            float a10 = acc[ms][n8][2] + bv.x, a11 = acc[ms][n8][3] + bv.y;
            if (EPI == 0) {
                *(float2*)&C[(size_t)r0 * N + c]       = make_float2(a00, a01);
                *(float2*)&C[(size_t)(r0 + 8) * N + c] = make_float2(a10, a11);
            } else {
                if (n0 < 2048) {                       // Q: rotary + split
                    int j = (c & 127) >> 1;
                    float c0 = g_rcos[r0 * 64 + j],       s0 = g_rsin[r0 * 64 + j];
                    float c1 = g_rcos[(r0 + 8) * 64 + j], s1 = g_rsin[(r0 + 8) * 64 + j];
                    store_pair(g_qbhi, g_qblo, (size_t)r0 * DMODEL + c,
                               a00 * c0 - a01 * s0, a00 * s0 + a01 * c0);
                    store_pair(g_qbhi, g_qblo, (size_t)(r0 + 8) * DMODEL + c,
                               a10 * c1 - a11 * s1, a10 * s1 + a11 * c1);
                } else if (n0 < 2560) {                // K: rotary + split, [kvh][s][dh]
                    int kvh = (c - 2048) >> 7, dh = c & 127, j = dh >> 1;
                    float c0 = g_rcos[r0 * 64 + j],       s0 = g_rsin[r0 * 64 + j];
                    float c1 = g_rcos[(r0 + 8) * 64 + j], s1 = g_rsin[(r0 + 8) * 64 + j];
                    size_t base = ((size_t)kvh * SEQ + r0) * DHEAD + dh;
                    store_pair(g_kbhi, g_kblo, base,
                               a00 * c0 - a01 * s0, a00 * s0 + a01 * c0);
                    store_pair(g_kbhi, g_kblo, base + 8 * DHEAD,
                               a10 * c1 - a11 * s1, a10 * s1 + a11 * c1);
                } else {                               // V: split + transpose [kvh][dh][s]
                    int kvh = (c - 2560) >> 7, dh = c & 127;
                    size_t b0 = ((size_t)kvh * DHEAD + dh) * SEQ;
                    size_t b1 = b0 + SEQ;
                    __nv_bfloat16 h, l;
                    split1(a00, h, l); g_vthi[b0 + r0] = h;     g_vtlo[b0 + r0] = l;
                    split1(a01, h, l); g_vthi[b1 + r0] = h;     g_vtlo[b1 + r0] = l;
                    split1(a10, h, l); g_vthi[b0 + r0 + 8] = h; g_vtlo[b0 + r0 + 8] = l;
                    split1(a11, h, l); g_vthi[b1 + r0 + 8] = h; g_vtlo[b1 + r0 + 8] = l;
                }
            }
        }
    }
}

// ---------------- flash attention (R4 design: Q in smem, 2-stage KV) ----------------
#define SMQ 0
#define SMK 65536
#define SMV 131072
#define ATT_SMEM 196608

__device__ __forceinline__ void load_kv_stage(uint32_t smb, int buf, int kv0, int tid,
                                              const __nv_bfloat16* khi, const __nv_bfloat16* klo,
                                              const __nv_bfloat16* vhi, const __nv_bfloat16* vlo) {
    #pragma unroll
    for (int sb = 0; sb < 4; sb++) {
        int isl = sb >> 1, b = sb & 1;
        const __nv_bfloat16* src = isl ? klo : khi;
        #pragma unroll
        for (int i = 0; i < 2; i++) {
            int c = tid + i * 256;
            int r = c >> 3, ch = c & 7;
            cp16(smb + SMK + buf * 32768 + sb * 8192 + SWZ(r * 128 + ch * 16),
                 src + (size_t)(kv0 + r) * DHEAD + b * 64 + ch * 8);
        }
    }
    #pragma unroll
    for (int isl = 0; isl < 2; isl++) {
        const __nv_bfloat16* src = isl ? vlo : vhi;
        #pragma unroll
        for (int i = 0; i < 4; i++) {
            int c = tid + i * 256;
            int d = c >> 3, ch = c & 7;
            cp16(smb + SMV + buf * 32768 + isl * 16384 + SWZ(d * 128 + ch * 16),
                 src + (size_t)d * SEQ + kv0 + ch * 8);
        }
    }
}

__global__ __launch_bounds__(256, 1) void attn_mma() {
    extern __shared__ char sm[];
    const uint32_t smb = smem_u32(sm);
    const int tid = threadIdx.x;
    const int wid = tid >> 5, lid = tid & 31;
    const int qb = (int)(gridDim.x - 1) - (int)blockIdx.x;
    const int h = blockIdx.y;
    const int kvh = h >> 2;
    const int q0 = qb * 128;
    const int nkv = 2 * qb + 2;
    const int w16 = wid * 16;

    const int arow = lid & 15;
    const int asel = (lid >> 4) * 16;
    const int brow = ((lid >> 4) << 3) + (lid & 7);
    const int bsel = ((lid >> 3) & 1) * 16;

    const __nv_bfloat16* khi = g_kbhi + (size_t)kvh * SEQ * DHEAD;
    const __nv_bfloat16* klo = g_kblo + (size_t)kvh * SEQ * DHEAD;
    const __nv_bfloat16* vhi = g_vthi + (size_t)kvh * DHEAD * SEQ;
    const __nv_bfloat16* vlo = g_vtlo + (size_t)kvh * DHEAD * SEQ;

    // prologue: Q tile (once) + KV stage 0
    #pragma unroll
    for (int sb = 0; sb < 4; sb++) {
        int isl = sb >> 1, b = sb & 1;
        const __nv_bfloat16* src = isl ? g_qblo : g_qbhi;
        #pragma unroll
        for (int i = 0; i < 4; i++) {
            int c = tid + i * 256;
            int r = c >> 3, ch = c & 7;
            cp16(smb + SMQ + sb * 16384 + SWZ(r * 128 + ch * 16),
                 src + (size_t)(q0 + r) * DMODEL + h * DHEAD + b * 64 + ch * 8);
        }
    }
    load_kv_stage(smb, 0, 0, tid, khi, klo, vhi, vlo);
    CP_COMMIT();

    float oacc[16][4];
    #pragma unroll
    for (int i = 0; i < 16; i++)
        #pragma unroll
        for (int j = 0; j < 4; j++) oacc[i][j] = 0.f;
    float m2[2] = {-1e30f, -1e30f};
    float l2[2] = {0.f, 0.f};
    const float KE = (float)(1.4426950408889634 / 11.313708498984761);

    for (int kb = 0; kb < nkv; kb++) {
        if (kb + 1 < nkv) {
            load_kv_stage(smb, (kb + 1) & 1, (kb + 1) * 64, tid, khi, klo, vhi, vlo);
            CP_COMMIT();
            asm volatile("cp.async.wait_group 1;" ::: "memory");
        } else {
            asm volatile("cp.async.wait_group 0;" ::: "memory");
        }
        __syncthreads();

        const uint32_t kbase = smb + SMK + (kb & 1) * 32768;
        const uint32_t vbase = smb + SMV + (kb & 1) * 32768;

        // ---- S = Q K^T ----
        float sacc[8][4];
        #pragma unroll
        for (int i = 0; i < 8; i++)
            #pragma unroll
            for (int j = 0; j < 4; j++) sacc[i][j] = 0.f;

        #pragma unroll
        for (int kk = 0; kk < 8; kk++) {
            int b = kk >> 2, koff = (kk & 3) * 32;
            uint32_t ah[4], al[4];
            uint32_t qoff = smb + SMQ + b * 16384 + SWZ((w16 + arow) * 128 + koff + asel);
            ldsm4(ah, qoff);
            ldsm4(al, qoff + 32768);
            #pragma unroll
            for (int ns = 0; ns < 4; ns++) {
                uint32_t bh[4], bl[4];
                uint32_t boff = kbase + b * 8192 + SWZ((ns * 16 + brow) * 128 + koff + bsel);
                ldsm4(bh, boff);
                ldsm4(bl, boff + 16384);
                mma_bf16(sacc[2 * ns],     ah, bh);     mma_bf16(sacc[2 * ns],     ah, bl);     mma_bf16(sacc[2 * ns],     al, bh);
                mma_bf16(sacc[2 * ns + 1], ah, bh + 2); mma_bf16(sacc[2 * ns + 1], ah, bl + 2); mma_bf16(sacc[2 * ns + 1], al, bh + 2);
            }
        }

        // ---- online softmax ----
        const int kv0 = kb * 64;
        const bool dodiag = (kb >= nkv - 2);
        #pragma unroll
        for (int g = 0; g < 2; g++) {
            int grow = q0 + w16 + (lid >> 2) + g * 8;
            if (dodiag) {
                #pragma unroll
                for (int n8 = 0; n8 < 8; n8++) {
                    int col = kv0 + n8 * 8 + (lid & 3) * 2;
                    if (col > grow)     sacc[n8][2 * g]     = -1e30f;
                    if (col + 1 > grow) sacc[n8][2 * g + 1] = -1e30f;
                }
            }
            float mt = -1e30f;
            #pragma unroll
            for (int n8 = 0; n8 < 8; n8++)
                mt = fmaxf(mt, fmaxf(sacc[n8][2 * g], sacc[n8][2 * g + 1]));
            mt = fmaxf(mt, __shfl_xor_sync(0xffffffffu, mt, 1));
            mt = fmaxf(mt, __shfl_xor_sync(0xffffffffu, mt, 2));
            float mnew = fmaxf(m2[g], mt);
            float alpha = ex2f((m2[g] - mnew) * KE);
            float ls = 0.f;
            #pragma unroll
            for (int n8 = 0; n8 < 8; n8++) {
                float p0 = ex2f((sacc[n8][2 * g]     - mnew) * KE);
                float p1 = ex2f((sacc[n8][2 * g + 1] - mnew) * KE);
                sacc[n8][2 * g] = p0; sacc[n8][2 * g + 1] = p1;
                ls += p0 + p1;
            }
            ls += __shfl_xor_sync(0xffffffffu, ls, 1);
            ls += __shfl_xor_sync(0xffffffffu, ls, 2);
            l2[g] = l2[g] * alpha + ls;
            m2[g] = mnew;
            #pragma unroll
            for (int t = 0; t < 16; t++) {
                oacc[t][2 * g]     *= alpha;
                oacc[t][2 * g + 1] *= alpha;
            }
        }

        // ---- O += P V ----
        #pragma unroll
        for (int t = 0; t < 4; t++) {
            uint32_t pa[4], pl[4];
            split2(sacc[2 * t][0],     sacc[2 * t][1],     pa[0], pl[0]);
            split2(sacc[2 * t][2],     sacc[2 * t][3],     pa[1], pl[1]);
            split2(sacc[2 * t + 1][0], sacc[2 * t + 1][1], pa[2], pl[2]);
            split2(sacc[2 * t + 1][2], sacc[2 * t + 1][3], pa[3], pl[3]);
            #pragma unroll
            for (int ns = 0; ns < 8; ns++) {
                uint32_t vh[4], vl[4];
                uint32_t voff = vbase + SWZ((ns * 16 + brow) * 128 + t * 32 + bsel);
                ldsm4(vh, voff);
                ldsm4(vl, voff + 16384);
                mma_bf16(oacc[2 * ns],     pa, vh);     mma_bf16(oacc[2 * ns],     pa, vl);     mma_bf16(oacc[2 * ns],     pl, vh);
                mma_bf16(oacc[2 * ns + 1], pa, vh + 2); mma_bf16(oacc[2 * ns + 1], pa, vl + 2); mma_bf16(oacc[2 * ns + 1], pl, vh + 2);
            }
        }
        __syncthreads();
    }

    // ---- epilogue ----
    float inv0 = 1.f / l2[0], inv1 = 1.f / l2[1];
    int r0 = q0 + w16 + (lid >> 2);
    int cb = h * DHEAD + (lid & 3) * 2;
    #pragma unroll
    for (int n8 = 0; n8 < 16; n8++) {
        int col = cb + n8 * 8;
        store_pair(g_zhi, g_zlo, (size_t)r0 * DMODEL + col,
                   oacc[n8][0] * inv0, oacc[n8][1] * inv0);
        store_pair(g_zhi, g_zlo, (size_t)(r0 + 8) * DMODEL + col,
                   oacc[n8][2] * inv1, oacc[n8][3] * inv1);
    }
}

// ---------------- launcher ----------------
extern "C" void kernel_launch(void* const* d_in, const int* in_sizes, int n_in,
                              void* d_out, int out_size) {
    const float* x  = (const float*)d_in[0];
    const float* WQ = (const float*)d_in[1];
    const float* WK = (const float*)d_in[2];
    const float* WV = (const float*)d_in[3];
    const float* WO = (const float*)d_in[4];
    const float* bQ = (const float*)d_in[5];
    const float* bK = (const float*)d_in[6];
    const float* bV = (const float*)d_in[7];
    const float* bO = (const float*)d_in[8];
    float* out = (float*)d_out;

    float* bcat;
    __nv_bfloat16 *xhi, *xlo, *zhi, *zlo, *Wthi, *Wtlo, *WOthi, *WOtlo;
    cudaGetSymbolAddress((void**)&bcat,  g_bcat);
    cudaGetSymbolAddress((void**)&xhi,   g_xhi);
    cudaGetSymbolAddress((void**)&xlo,   g_xlo);
    cudaGetSymbolAddress((void**)&zhi,   g_zhi);
    cudaGetSymbolAddress((void**)&zlo,   g_zlo);
    cudaGetSymbolAddress((void**)&Wthi,  g_Wthi);
    cudaGetSymbolAddress((void**)&Wtlo,  g_Wtlo);
    cudaGetSymbolAddress((void**)&WOthi, g_WOthi);
    cudaGetSymbolAddress((void**)&WOtlo, g_WOtlo);

    cudaFuncSetAttribute(gemm3<0>, cudaFuncAttributeMaxDynamicSharedMemorySize, GSMEM);
    cudaFuncSetAttribute(gemm3<1>, cudaFuncAttributeMaxDynamicSharedMemorySize, GSMEM);
    cudaFuncSetAttribute(attn_mma, cudaFuncAttributeMaxDynamicSharedMemorySize, ATT_SMEM);

    // 1) weight repacks (+rotary table) + input split
    repack_wqkv_rot<<<REP_BLOCKS + (SEQ * 64) / 256, 256>>>(WQ, WK, WV, bQ, bK, bV);
    repack_wo<<<(DMODEL * KDIM + 255) / 256, 256>>>(WO);
    split_f32<<<(SEQ * DMODEL + 255) / 256, 256>>>(x, xhi, xlo, SEQ * DMODEL);

    // 2) QKV projection + fused bias/rotary/split/layout epilogue
    {
        dim3 grid(SEQ / BM, NCOLS / BN);
        gemm3<1><<<grid, 512, GSMEM>>>(xhi, xlo, Wthi, Wtlo, bcat, nullptr, NCOLS);
    }
    // 3) causal flash attention -> zhi/zlo
    {
        dim3 grid(SEQ / 128, NH);
        attn_mma<<<grid, 256, ATT_SMEM>>>();
    }
    // 4) O-projection
    {
        dim3 grid(SEQ / BM, DMODEL / BN);
        gemm3<0><<<grid, 512, GSMEM>>>(zhi, zlo, WOthi, WOtlo, bO, out, DMODEL);
    }
}

// round 7
// speedup vs baseline: 1.0972x; 1.0972x over previous
#include <cuda_runtime.h>
#include <cuda_bf16.h>
#include <cuda_fp16.h>
#include <math.h>
#include <stdint.h>

#define SEQ     4096
#define DMODEL  2048
#define DHEAD   128
#define NH      16
#define NKV     4
#define NCOLS   3072
#define KDIM    2048

// ---------------- scratch ----------------
__device__ __align__(256) float g_bcat[NCOLS];
__device__ __align__(256) __nv_bfloat16 g_xhi[SEQ * DMODEL];
__device__ __align__(256) __nv_bfloat16 g_xlo[SEQ * DMODEL];
__device__ __align__(256) __nv_bfloat16 g_zhi[SEQ * DMODEL];
__device__ __align__(256) __nv_bfloat16 g_zlo[SEQ * DMODEL];
__device__ __align__(256) __nv_bfloat16 g_Wthi[NCOLS * KDIM];
__device__ __align__(256) __nv_bfloat16 g_Wtlo[NCOLS * KDIM];
__device__ __align__(256) __nv_bfloat16 g_WOthi[DMODEL * KDIM];
__device__ __align__(256) __nv_bfloat16 g_WOtlo[DMODEL * KDIM];
__device__ __align__(256) __nv_bfloat16 g_qbhi[SEQ * DMODEL];
__device__ __align__(256) __nv_bfloat16 g_qblo[SEQ * DMODEL];
__device__ __align__(256) __nv_bfloat16 g_kbhi[NKV * SEQ * DHEAD];
__device__ __align__(256) __nv_bfloat16 g_kblo[NKV * SEQ * DHEAD];
__device__ __align__(256) __half g_vthi[NKV * DHEAD * SEQ];   // V^T fp16 hi
__device__ __align__(256) __half g_vtlo[NKV * DHEAD * SEQ];   // V^T fp16 lo (exact residual)
__device__ __align__(256) float g_rcos[SEQ * 64];
__device__ __align__(256) float g_rsin[SEQ * 64];

// ---------------- helpers ----------------
__device__ __forceinline__ uint32_t smem_u32(const void* p) {
    uint32_t a;
    asm("{ .reg .u64 t; cvta.to.shared.u64 t, %1; cvt.u32.u64 %0, t; }" : "=r"(a) : "l"(p));
    return a;
}
__device__ __forceinline__ void cp16(uint32_t s, const void* g) {
    asm volatile("cp.async.cg.shared.global [%0], [%1], 16;" :: "r"(s), "l"(g));
}
#define CP_COMMIT() asm volatile("cp.async.commit_group;" ::: "memory")
__device__ __forceinline__ void ldsm4(uint32_t* r, uint32_t addr) {
    asm volatile("ldmatrix.sync.aligned.m8n8.x4.shared.b16 {%0,%1,%2,%3}, [%4];"
        : "=r"(r[0]), "=r"(r[1]), "=r"(r[2]), "=r"(r[3]) : "r"(addr));
}
__device__ __forceinline__ void mma_bf16(float* d, const uint32_t* a, const uint32_t* b) {
    asm volatile("mma.sync.aligned.m16n8k16.row.col.f32.bf16.bf16.f32 "
        "{%0,%1,%2,%3}, {%4,%5,%6,%7}, {%8,%9}, {%0,%1,%2,%3};"
        : "+f"(d[0]), "+f"(d[1]), "+f"(d[2]), "+f"(d[3])
        : "r"(a[0]), "r"(a[1]), "r"(a[2]), "r"(a[3]), "r"(b[0]), "r"(b[1]));
}
__device__ __forceinline__ void mma_f16(float* d, const uint32_t* a, const uint32_t* b) {
    asm volatile("mma.sync.aligned.m16n8k16.row.col.f32.f16.f16.f32 "
        "{%0,%1,%2,%3}, {%4,%5,%6,%7}, {%8,%9}, {%0,%1,%2,%3};"
        : "+f"(d[0]), "+f"(d[1]), "+f"(d[2]), "+f"(d[3])
        : "r"(a[0]), "r"(a[1]), "r"(a[2]), "r"(a[3]), "r"(b[0]), "r"(b[1]));
}
__device__ __forceinline__ float ex2f(float x) {
    float y; asm("ex2.approx.ftz.f32 %0, %1;" : "=f"(y) : "f"(x)); return y;
}
// pack (p0 -> lo16, p1 -> hi16) as fp16x2; PTX: first source goes to upper half
__device__ __forceinline__ uint32_t f16x2(float p0, float p1) {
    uint32_t r;
    asm("cvt.rn.f16x2.f32 %0, %1, %2;" : "=r"(r) : "f"(p1), "f"(p0));
    return r;
}
__device__ __forceinline__ void split1(float v, __nv_bfloat16& h, __nv_bfloat16& l) {
    h = __float2bfloat16(v);
    l = __float2bfloat16(v - __bfloat162float(h));
}
__device__ __forceinline__ void split1h(float v, __half& h, __half& l) {
    h = __float2half_rn(v);
    l = __float2half_rn(v - __half2float(h));
}
__device__ __forceinline__ void store_pair(__nv_bfloat16* hi, __nv_bfloat16* lo,
                                           size_t off, float v0, float v1) {
    __nv_bfloat16 h0, l0, h1, l1;
    split1(v0, h0, l0);
    split1(v1, h1, l1);
    *(__nv_bfloat162*)(hi + off) = __nv_bfloat162(h0, h1);
    *(__nv_bfloat162*)(lo + off) = __nv_bfloat162(l0, l1);
}
#define SWZ(off) ((off) ^ (((off) >> 3) & 0x70))

// ---------------- repack QKV weights + bias + rotary table (merged) ----------------
#define REP_BLOCKS ((NCOLS * KDIM) / 256)
__global__ void repack_wqkv_rot(const float* __restrict__ WQ, const float* __restrict__ WK,
                                const float* __restrict__ WV, const float* __restrict__ bQ,
                                const float* __restrict__ bK, const float* __restrict__ bV) {
    if (blockIdx.x >= REP_BLOCKS) {
        int idx = (blockIdx.x - REP_BLOCKS) * 256 + threadIdx.x;
        if (idx >= SEQ * 64) return;
        int j = idx & 63, s = idx >> 6;
        double dfreq = pow(10000.0, -(double)j / 64.0);
        float freq = (float)dfreq;
        float angle = (float)s * freq;
        double da = (double)angle;
        g_rcos[idx] = (float)cos(da);
        g_rsin[idx] = (float)sin(da);
        return;
    }
    int idx = blockIdx.x * 256 + threadIdx.x;
    if (idx < NCOLS) {
        float b;
        if      (idx < 2048) b = bQ[idx];
        else if (idx < 2560) b = bK[idx - 2048];
        else                 b = bV[idx - 2560];
        g_bcat[idx] = b;
    }
    int n = idx >> 11;
    int k = idx & 2047;
    float v;
    if (n < 2048) {
        int head = n >> 7, h = n & 127;
        v = WQ[((size_t)head * KDIM + k) * DHEAD + h];
    } else if (n < 2560) {
        int head = (n - 2048) >> 7, h = n & 127;
        v = WK[((size_t)head * KDIM + k) * DHEAD + h];
    } else {
        int head = (n - 2560) >> 7, h = n & 127;
        v = WV[((size_t)head * KDIM + k) * DHEAD + h];
    }
    __nv_bfloat16 hi, lo;
    split1(v, hi, lo);
    g_Wthi[idx] = hi;
    g_Wtlo[idx] = lo;
}

__global__ void repack_wo(const float* __restrict__ WO) {
    int idx = blockIdx.x * blockDim.x + threadIdx.x;
    if (idx >= DMODEL * KDIM) return;
    int k = idx >> 11;
    int m = idx & 2047;
    __nv_bfloat16 hi, lo;
    split1(WO[idx], hi, lo);
    g_WOthi[(size_t)m * KDIM + k] = hi;
    g_WOtlo[(size_t)m * KDIM + k] = lo;
}

__global__ void split_f32(const float* __restrict__ src, __nv_bfloat16* __restrict__ hi,
                          __nv_bfloat16* __restrict__ lo, int n) {
    int i = blockIdx.x * blockDim.x + threadIdx.x;
    if (i >= n) return;
    __nv_bfloat16 h, l;
    split1(src[i], h, l);
    hi[i] = h;
    lo[i] = l;
}

// ---------------- mma.sync bf16x3 GEMM: R3 mainloop (256 thr, 64x32 warp tile) ----------------
// EPI=0: C = A*B^T + bias. EPI=1: fused QKV epilogue (rotary + splits + layouts).
#define BM 128
#define BN 128
#define BKT 64
#define MATB 16384
#define BUFB (4 * MATB)        // 64 KB per stage
#define GSMEM (2 * BUFB)       // 128 KB
#define NSTG (KDIM / BKT)      // 32

__device__ __forceinline__ void load_stage(uint32_t bb, int k0, int m0, int n0, int tid,
                                           const __nv_bfloat16* Ahi, const __nv_bfloat16* Alo,
                                           const __nv_bfloat16* Bhi, const __nv_bfloat16* Blo) {
    #pragma unroll
    for (int i = 0; i < 4; i++) {
        int c = tid + i * 256;
        int r = c >> 3, ch = c & 7;
        uint32_t so = bb + SWZ(r * 128 + ch * 16);
        size_t ga = (size_t)(m0 + r) * KDIM + k0 + ch * 8;
        size_t gb = (size_t)(n0 + r) * KDIM + k0 + ch * 8;
        cp16(so,            Ahi + ga);
        cp16(so + MATB,     Alo + ga);
        cp16(so + 2 * MATB, Bhi + gb);
        cp16(so + 3 * MATB, Blo + gb);
    }
}

template<int EPI>
__global__ __launch_bounds__(256, 1) void gemm3(
    const __nv_bfloat16* __restrict__ Ahi, const __nv_bfloat16* __restrict__ Alo,
    const __nv_bfloat16* __restrict__ Bhi, const __nv_bfloat16* __restrict__ Blo,
    const float* __restrict__ bias, float* __restrict__ C, int N)
{
    extern __shared__ char sm[];
    const uint32_t smb = smem_u32(sm);
    const int tid = threadIdx.x;
    const int wid = tid >> 5, lid = tid & 31;
    const int m0 = blockIdx.x * BM, n0 = blockIdx.y * BN;
    const int wm = (wid & 1) * 64;
    const int wn = (wid >> 1) * 32;

    float acc[4][4][4];
    #pragma unroll
    for (int i = 0; i < 4; i++)
        #pragma unroll
        for (int j = 0; j < 4; j++)
            #pragma unroll
            for (int k = 0; k < 4; k++) acc[i][j][k] = 0.f;

    const int arow = lid & 15;
    const int asel = (lid >> 4) * 16;
    const int brow = ((lid >> 4) << 3) + (lid & 7);
    const int bsel = ((lid >> 3) & 1) * 16;

    load_stage(smb, 0, m0, n0, tid, Ahi, Alo, Bhi, Blo);
    CP_COMMIT();

    for (int s = 0; s < NSTG; s++) {
        if (s + 1 < NSTG) {
            load_stage(smb + ((s + 1) & 1) * BUFB, (s + 1) * BKT, m0, n0, tid,
                       Ahi, Alo, Bhi, Blo);
            CP_COMMIT();
            asm volatile("cp.async.wait_group 1;" ::: "memory");
        } else {
            asm volatile("cp.async.wait_group 0;" ::: "memory");
        }
        __syncthreads();

        uint32_t bb = smb + (s & 1) * BUFB;
        #pragma unroll
        for (int kk = 0; kk < 4; kk++) {
            uint32_t ah[4][4], al[4][4];
            #pragma unroll
            for (int ms = 0; ms < 4; ms++) {
                uint32_t off = SWZ((wm + ms * 16 + arow) * 128 + kk * 32 + asel);
                ldsm4(ah[ms], bb + off);
                ldsm4(al[ms], bb + MATB + off);
            }
            uint32_t bh[2][4], bl[2][4];
            #pragma unroll
            for (int ns = 0; ns < 2; ns++) {
                uint32_t off = SWZ((wn + ns * 16 + brow) * 128 + kk * 32 + bsel);
                ldsm4(bh[ns], bb + 2 * MATB + off);
                ldsm4(bl[ns], bb + 3 * MATB + off);
            }
            #pragma unroll
            for (int ms = 0; ms < 4; ms++)
                #pragma unroll
                for (int n8 = 0; n8 < 4; n8++) {
                    const uint32_t* ph = &bh[n8 >> 1][(n8 & 1) * 2];
                    const uint32_t* pl = &bl[n8 >> 1][(n8 & 1) * 2];
                    mma_bf16(acc[ms][n8], ah[ms], ph);
                    mma_bf16(acc[ms][n8], ah[ms], pl);
                    mma_bf16(acc[ms][n8], al[ms], ph);
                }
        }
        __syncthreads();
    }

    const int erow = lid >> 2, ecol = (lid & 3) * 2;
    #pragma unroll
    for (int ms = 0; ms < 4; ms++) {
        int r0 = m0 + wm + ms * 16 + erow;
        #pragma unroll
        for (int n8 = 0; n8 < 4; n8++) {
            int c = n0 + wn + n8 * 8 + ecol;
            float2 bv = *(const float2*)&bias[c];
            float a00 = acc[ms][n8][0] + bv.x, a01 = acc[ms][n8][1] + bv.y;
            float a10 = acc[ms][n8][2] + bv.x, a11 = acc[ms][n8][3] + bv.y;
            if (EPI == 0) {
                *(float2*)&C[(size_t)r0 * N + c]       = make_float2(a00, a01);
                *(float2*)&C[(size_t)(r0 + 8) * N + c] = make_float2(a10, a11);
            } else {
                if (n0 < 2048) {                       // Q: rotary + split
                    int j = (c & 127) >> 1;
                    float c0 = g_rcos[r0 * 64 + j],       s0 = g_rsin[r0 * 64 + j];
                    float c1 = g_rcos[(r0 + 8) * 64 + j], s1 = g_rsin[(r0 + 8) * 64 + j];
                    store_pair(g_qbhi, g_qblo, (size_t)r0 * DMODEL + c,
                               a00 * c0 - a01 * s0, a00 * s0 + a01 * c0);
                    store_pair(g_qbhi, g_qblo, (size_t)(r0 + 8) * DMODEL + c,
                               a10 * c1 - a11 * s1, a10 * s1 + a11 * c1);
                } else if (n0 < 2560) {                // K: rotary + split, [kvh][s][dh]
                    int kvh = (c - 2048) >> 7, dh = c & 127, j = dh >> 1;
                    float c0 = g_rcos[r0 * 64 + j],       s0 = g_rsin[r0 * 64 + j];
                    float c1 = g_rcos[(r0 + 8) * 64 + j], s1 = g_rsin[(r0 + 8) * 64 + j];
                    size_t base = ((size_t)kvh * SEQ + r0) * DHEAD + dh;
                    store_pair(g_kbhi, g_kblo, base,
                               a00 * c0 - a01 * s0, a00 * s0 + a01 * c0);
                    store_pair(g_kbhi, g_kblo, base + 8 * DHEAD,
                               a10 * c1 - a11 * s1, a10 * s1 + a11 * c1);
                } else {                               // V: fp16 split + transpose [kvh][dh][s]
                    int kvh = (c - 2560) >> 7, dh = c & 127;
                    size_t b0 = ((size_t)kvh * DHEAD + dh) * SEQ;
                    size_t b1 = b0 + SEQ;
                    __half h, l;
                    split1h(a00, h, l); g_vthi[b0 + r0] = h;     g_vtlo[b0 + r0] = l;
                    split1h(a01, h, l); g_vthi[b1 + r0] = h;     g_vtlo[b1 + r0] = l;
                    split1h(a10, h, l); g_vthi[b0 + r0 + 8] = h; g_vtlo[b0 + r0 + 8] = l;
                    split1h(a11, h, l); g_vthi[b1 + r0 + 8] = h; g_vtlo[b1 + r0 + 8] = l;
                }
            }
        }
    }
}

// ---------------- flash attention (Q in smem, 2-stage KV; fp16 P·V) ----------------
#define SMQ 0
#define SMK 65536
#define SMV 131072
#define ATT_SMEM 196608

__device__ __forceinline__ void load_kv_stage(uint32_t smb, int buf, int kv0, int tid,
                                              const __nv_bfloat16* khi, const __nv_bfloat16* klo,
                                              const __half* vhi, const __half* vlo) {
    #pragma unroll
    for (int sb = 0; sb < 4; sb++) {
        int isl = sb >> 1, b = sb & 1;
        const __nv_bfloat16* src = isl ? klo : khi;
        #pragma unroll
        for (int i = 0; i < 2; i++) {
            int c = tid + i * 256;
            int r = c >> 3, ch = c & 7;
            cp16(smb + SMK + buf * 32768 + sb * 8192 + SWZ(r * 128 + ch * 16),
                 src + (size_t)(kv0 + r) * DHEAD + b * 64 + ch * 8);
        }
    }
    #pragma unroll
    for (int isl = 0; isl < 2; isl++) {
        const __half* src = isl ? vlo : vhi;
        #pragma unroll
        for (int i = 0; i < 4; i++) {
            int c = tid + i * 256;
            int d = c >> 3, ch = c & 7;
            cp16(smb + SMV + buf * 32768 + isl * 16384 + SWZ(d * 128 + ch * 16),
                 src + (size_t)d * SEQ + kv0 + ch * 8);
        }
    }
}

__global__ __launch_bounds__(256, 1) void attn_mma() {
    extern __shared__ char sm[];
    const uint32_t smb = smem_u32(sm);
    const int tid = threadIdx.x;
    const int wid = tid >> 5, lid = tid & 31;
    const int qb = (int)(gridDim.x - 1) - (int)blockIdx.x;
    const int h = blockIdx.y;
    const int kvh = h >> 2;
    const int q0 = qb * 128;
    const int nkv = 2 * qb + 2;
    const int w16 = wid * 16;

    const int arow = lid & 15;
    const int asel = (lid >> 4) * 16;
    const int brow = ((lid >> 4) << 3) + (lid & 7);
    const int bsel = ((lid >> 3) & 1) * 16;

    const __nv_bfloat16* khi = g_kbhi + (size_t)kvh * SEQ * DHEAD;
    const __nv_bfloat16* klo = g_kblo + (size_t)kvh * SEQ * DHEAD;
    const __half* vhi = g_vthi + (size_t)kvh * DHEAD * SEQ;
    const __half* vlo = g_vtlo + (size_t)kvh * DHEAD * SEQ;

    // prologue: Q tile (once) + KV stage 0
    #pragma unroll
    for (int sb = 0; sb < 4; sb++) {
        int isl = sb >> 1, b = sb & 1;
        const __nv_bfloat16* src = isl ? g_qblo : g_qbhi;
        #pragma unroll
        for (int i = 0; i < 4; i++) {
            int c = tid + i * 256;
            int r = c >> 3, ch = c & 7;
            cp16(smb + SMQ + sb * 16384 + SWZ(r * 128 + ch * 16),
                 src + (size_t)(q0 + r) * DMODEL + h * DHEAD + b * 64 + ch * 8);
        }
    }
    load_kv_stage(smb, 0, 0, tid, khi, klo, vhi, vlo);
    CP_COMMIT();

    float oacc[16][4];
    #pragma unroll
    for (int i = 0; i < 16; i++)
        #pragma unroll
        for (int j = 0; j < 4; j++) oacc[i][j] = 0.f;
    float m2[2] = {-1e30f, -1e30f};
    float l2[2] = {0.f, 0.f};
    const float KE = (float)(1.4426950408889634 / 11.313708498984761);

    for (int kb = 0; kb < nkv; kb++) {
        if (kb + 1 < nkv) {
            load_kv_stage(smb, (kb + 1) & 1, (kb + 1) * 64, tid, khi, klo, vhi, vlo);
            CP_COMMIT();
            asm volatile("cp.async.wait_group 1;" ::: "memory");
        } else {
            asm volatile("cp.async.wait_group 0;" ::: "memory");
        }
        __syncthreads();

        const uint32_t kbase = smb + SMK + (kb & 1) * 32768;
        const uint32_t vbase = smb + SMV + (kb & 1) * 32768;

        // ---- S = Q K^T (bf16x3) ----
        float sacc[8][4];
        #pragma unroll
        for (int i = 0; i < 8; i++)
            #pragma unroll
            for (int j = 0; j < 4; j++) sacc[i][j] = 0.f;

        #pragma unroll
        for (int kk = 0; kk < 8; kk++) {
            int b = kk >> 2, koff = (kk & 3) * 32;
            uint32_t ah[4], al[4];
            uint32_t qoff = smb + SMQ + b * 16384 + SWZ((w16 + arow) * 128 + koff + asel);
            ldsm4(ah, qoff);
            ldsm4(al, qoff + 32768);
            #pragma unroll
            for (int ns = 0; ns < 4; ns++) {
                uint32_t bh[4], bl[4];
                uint32_t boff = kbase + b * 8192 + SWZ((ns * 16 + brow) * 128 + koff + bsel);
                ldsm4(bh, boff);
                ldsm4(bl, boff + 16384);
                mma_bf16(sacc[2 * ns],     ah, bh);     mma_bf16(sacc[2 * ns],     ah, bl);     mma_bf16(sacc[2 * ns],     al, bh);
                mma_bf16(sacc[2 * ns + 1], ah, bh + 2); mma_bf16(sacc[2 * ns + 1], ah, bl + 2); mma_bf16(sacc[2 * ns + 1], al, bh + 2);
            }
        }

        // ---- online softmax ----
        const int kv0 = kb * 64;
        const bool dodiag = (kb >= nkv - 2);
        #pragma unroll
        for (int g = 0; g < 2; g++) {
            int grow = q0 + w16 + (lid >> 2) + g * 8;
            if (dodiag) {
                #pragma unroll
                for (int n8 = 0; n8 < 8; n8++) {
                    int col = kv0 + n8 * 8 + (lid & 3) * 2;
                    if (col > grow)     sacc[n8][2 * g]     = -1e30f;
                    if (col + 1 > grow) sacc[n8][2 * g + 1] = -1e30f;
                }
            }
            float mt = -1e30f;
            #pragma unroll
            for (int n8 = 0; n8 < 8; n8++)
                mt = fmaxf(mt, fmaxf(sacc[n8][2 * g], sacc[n8][2 * g + 1]));
            mt = fmaxf(mt, __shfl_xor_sync(0xffffffffu, mt, 1));
            mt = fmaxf(mt, __shfl_xor_sync(0xffffffffu, mt, 2));
            float mnew = fmaxf(m2[g], mt);
            float alpha = ex2f((m2[g] - mnew) * KE);
            float ls = 0.f;
            #pragma unroll
            for (int n8 = 0; n8 < 8; n8++) {
                float p0 = ex2f((sacc[n8][2 * g]     - mnew) * KE);
                float p1 = ex2f((sacc[n8][2 * g + 1] - mnew) * KE);
                sacc[n8][2 * g] = p0; sacc[n8][2 * g + 1] = p1;
                ls += p0 + p1;
            }
            ls += __shfl_xor_sync(0xffffffffu, ls, 1);
            ls += __shfl_xor_sync(0xffffffffu, ls, 2);
            l2[g] = l2[g] * alpha + ls;
            m2[g] = mnew;
            #pragma unroll
            for (int t = 0; t < 16; t++) {
                oacc[t][2 * g]     *= alpha;
                oacc[t][2 * g + 1] *= alpha;
            }
        }

        // ---- O += P V  (P fp16 single, V fp16 hi+lo: 2 MMAs per pair) ----
        #pragma unroll
        for (int t = 0; t < 4; t++) {
            uint32_t pa[4];
            pa[0] = f16x2(sacc[2 * t][0],     sacc[2 * t][1]);
            pa[1] = f16x2(sacc[2 * t][2],     sacc[2 * t][3]);
            pa[2] = f16x2(sacc[2 * t + 1][0], sacc[2 * t + 1][1]);
            pa[3] = f16x2(sacc[2 * t + 1][2], sacc[2 * t + 1][3]);
            #pragma unroll
            for (int ns = 0; ns < 8; ns++) {
                uint32_t vh[4], vl[4];
                uint32_t voff = vbase + SWZ((ns * 16 + brow) * 128 + t * 32 + bsel);
                ldsm4(vh, voff);
                ldsm4(vl, voff + 16384);
                mma_f16(oacc[2 * ns],     pa, vh);     mma_f16(oacc[2 * ns],     pa, vl);
                mma_f16(oacc[2 * ns + 1], pa, vh + 2); mma_f16(oacc[2 * ns + 1], pa, vl + 2);
            }
        }
        __syncthreads();
    }

    // ---- epilogue ----
    float inv0 = 1.f / l2[0], inv1 = 1.f / l2[1];
    int r0 = q0 + w16 + (lid >> 2);
    int cb = h * DHEAD + (lid & 3) * 2;
    #pragma unroll
    for (int n8 = 0; n8 < 16; n8++) {
        int col = cb + n8 * 8;
        store_pair(g_zhi, g_zlo, (size_t)r0 * DMODEL + col,
                   oacc[n8][0] * inv0, oacc[n8][1] * inv0);
        store_pair(g_zhi, g_zlo, (size_t)(r0 + 8) * DMODEL + col,
                   oacc[n8][2] * inv1, oacc[n8][3] * inv1);
    }
}

// ---------------- launcher ----------------
extern "C" void kernel_launch(void* const* d_in, const int* in_sizes, int n_in,
                              void* d_out, int out_size) {
    const float* x  = (const float*)d_in[0];
    const float* WQ = (const float*)d_in[1];
    const float* WK = (const float*)d_in[2];
    const float* WV = (const float*)d_in[3];
    const float* WO = (const float*)d_in[4];
    const float* bQ = (const float*)d_in[5];
    const float* bK = (const float*)d_in[6];
    const float* bV = (const float*)d_in[7];
    const float* bO = (const float*)d_in[8];
    float* out = (float*)d_out;

    float* bcat;
    __nv_bfloat16 *xhi, *xlo, *zhi, *zlo, *Wthi, *Wtlo, *WOthi, *WOtlo;
    cudaGetSymbolAddress((void**)&bcat,  g_bcat);
    cudaGetSymbolAddress((void**)&xhi,   g_xhi);
    cudaGetSymbolAddress((void**)&xlo,   g_xlo);
    cudaGetSymbolAddress((void**)&zhi,   g_zhi);
    cudaGetSymbolAddress((void**)&zlo,   g_zlo);
    cudaGetSymbolAddress((void**)&Wthi,  g_Wthi);
    cudaGetSymbolAddress((void**)&Wtlo,  g_Wtlo);
    cudaGetSymbolAddress((void**)&WOthi, g_WOthi);
    cudaGetSymbolAddress((void**)&WOtlo, g_WOtlo);

    cudaFuncSetAttribute(gemm3<0>, cudaFuncAttributeMaxDynamicSharedMemorySize, GSMEM);
    cudaFuncSetAttribute(gemm3<1>, cudaFuncAttributeMaxDynamicSharedMemorySize, GSMEM);
    cudaFuncSetAttribute(attn_mma, cudaFuncAttributeMaxDynamicSharedMemorySize, ATT_SMEM);

    // 1) weight repacks (+rotary table) + input split
    repack_wqkv_rot<<<REP_BLOCKS + (SEQ * 64) / 256, 256>>>(WQ, WK, WV, bQ, bK, bV);
    repack_wo<<<(DMODEL * KDIM + 255) / 256, 256>>>(WO);
    split_f32<<<(SEQ * DMODEL + 255) / 256, 256>>>(x, xhi, xlo, SEQ * DMODEL);

    // 2) QKV projection + fused bias/rotary/split/layout epilogue
    {
        dim3 grid(SEQ / BM, NCOLS / BN);
        gemm3<1><<<grid, 256, GSMEM>>>(xhi, xlo, Wthi, Wtlo, bcat, nullptr, NCOLS);
    }
    // 3) causal flash attention -> zhi/zlo
    {
        dim3 grid(SEQ / 128, NH);
        attn_mma<<<grid, 256, ATT_SMEM>>>();
    }
    // 4) O-projection
    {
        dim3 grid(SEQ / BM, DMODEL / BN);
        gemm3<0><<<grid, 256, GSMEM>>>(zhi, zlo, WOthi, WOtlo, bO, out, DMODEL);
    }
}

// round 8
// speedup vs baseline: 1.3918x; 1.2684x over previous
#include <cuda_runtime.h>
#include <cuda_bf16.h>
#include <cuda_fp16.h>
#include <math.h>
#include <stdint.h>

#define SEQ     4096
#define DMODEL  2048
#define DHEAD   128
#define NH      16
#define NKV     4
#define NCOLS   3072
#define KDIM    2048

// ---------------- scratch ----------------
__device__ __align__(256) float g_bcat[NCOLS];
__device__ __align__(256) __half g_xhi[SEQ * DMODEL];      // x fp16 hi/lo split
__device__ __align__(256) __half g_xlo[SEQ * DMODEL];
__device__ __align__(256) __half g_zhi[SEQ * DMODEL];      // z fp16 hi/lo split
__device__ __align__(256) __half g_zlo[SEQ * DMODEL];
__device__ __align__(256) __half g_Wthi[NCOLS * KDIM];     // QKV W^T fp16 single
__device__ __align__(256) __half g_WOthi[DMODEL * KDIM];   // W_O^T fp16 single
__device__ __align__(256) __nv_bfloat16 g_qbhi[SEQ * DMODEL];   // Q bf16 hi/lo (S needs x3)
__device__ __align__(256) __nv_bfloat16 g_qblo[SEQ * DMODEL];
__device__ __align__(256) __nv_bfloat16 g_kbhi[NKV * SEQ * DHEAD];
__device__ __align__(256) __nv_bfloat16 g_kblo[NKV * SEQ * DHEAD];
__device__ __align__(256) __half g_vthi[NKV * DHEAD * SEQ];     // V^T fp16 single
__device__ __align__(256) float g_rcos[SEQ * 64];
__device__ __align__(256) float g_rsin[SEQ * 64];

// ---------------- helpers ----------------
__device__ __forceinline__ uint32_t smem_u32(const void* p) {
    uint32_t a;
    asm("{ .reg .u64 t; cvta.to.shared.u64 t, %1; cvt.u32.u64 %0, t; }" : "=r"(a) : "l"(p));
    return a;
}
__device__ __forceinline__ void cp16(uint32_t s, const void* g) {
    asm volatile("cp.async.cg.shared.global [%0], [%1], 16;" :: "r"(s), "l"(g));
}
#define CP_COMMIT() asm volatile("cp.async.commit_group;" ::: "memory")
__device__ __forceinline__ void ldsm4(uint32_t* r, uint32_t addr) {
    asm volatile("ldmatrix.sync.aligned.m8n8.x4.shared.b16 {%0,%1,%2,%3}, [%4];"
        : "=r"(r[0]), "=r"(r[1]), "=r"(r[2]), "=r"(r[3]) : "r"(addr));
}
__device__ __forceinline__ void mma_bf16(float* d, const uint32_t* a, const uint32_t* b) {
    asm volatile("mma.sync.aligned.m16n8k16.row.col.f32.bf16.bf16.f32 "
        "{%0,%1,%2,%3}, {%4,%5,%6,%7}, {%8,%9}, {%0,%1,%2,%3};"
        : "+f"(d[0]), "+f"(d[1]), "+f"(d[2]), "+f"(d[3])
        : "r"(a[0]), "r"(a[1]), "r"(a[2]), "r"(a[3]), "r"(b[0]), "r"(b[1]));
}
__device__ __forceinline__ void mma_f16(float* d, const uint32_t* a, const uint32_t* b) {
    asm volatile("mma.sync.aligned.m16n8k16.row.col.f32.f16.f16.f32 "
        "{%0,%1,%2,%3}, {%4,%5,%6,%7}, {%8,%9}, {%0,%1,%2,%3};"
        : "+f"(d[0]), "+f"(d[1]), "+f"(d[2]), "+f"(d[3])
        : "r"(a[0]), "r"(a[1]), "r"(a[2]), "r"(a[3]), "r"(b[0]), "r"(b[1]));
}
__device__ __forceinline__ float ex2f(float x) {
    float y; asm("ex2.approx.ftz.f32 %0, %1;" : "=f"(y) : "f"(x)); return y;
}
// pack (p0 -> lo16, p1 -> hi16) as fp16x2
__device__ __forceinline__ uint32_t f16x2(float p0, float p1) {
    uint32_t r;
    asm("cvt.rn.f16x2.f32 %0, %1, %2;" : "=r"(r) : "f"(p1), "f"(p0));
    return r;
}
__device__ __forceinline__ void split1(float v, __nv_bfloat16& h, __nv_bfloat16& l) {
    h = __float2bfloat16(v);
    l = __float2bfloat16(v - __bfloat162float(h));
}
__device__ __forceinline__ void split1h(float v, __half& h, __half& l) {
    h = __float2half_rn(v);
    l = __float2half_rn(v - __half2float(h));
}
__device__ __forceinline__ void store_pair(__nv_bfloat16* hi, __nv_bfloat16* lo,
                                           size_t off, float v0, float v1) {
    __nv_bfloat16 h0, l0, h1, l1;
    split1(v0, h0, l0);
    split1(v1, h1, l1);
    *(__nv_bfloat162*)(hi + off) = __nv_bfloat162(h0, h1);
    *(__nv_bfloat162*)(lo + off) = __nv_bfloat162(l0, l1);
}
__device__ __forceinline__ void store_pair_h(__half* hi, __half* lo,
                                             size_t off, float v0, float v1) {
    __half h0, l0, h1, l1;
    split1h(v0, h0, l0);
    split1h(v1, h1, l1);
    *(__half2*)(hi + off) = __half2(h0, h1);
    *(__half2*)(lo + off) = __half2(l0, l1);
}
#define SWZ(off) ((off) ^ (((off) >> 3) & 0x70))

// ---------------- repack QKV weights + bias + rotary table (merged) ----------------
#define REP_BLOCKS ((NCOLS * KDIM) / 256)
__global__ void repack_wqkv_rot(const float* __restrict__ WQ, const float* __restrict__ WK,
                                const float* __restrict__ WV, const float* __restrict__ bQ,
                                const float* __restrict__ bK, const float* __restrict__ bV) {
    if (blockIdx.x >= REP_BLOCKS) {
        int idx = (blockIdx.x - REP_BLOCKS) * 256 + threadIdx.x;
        if (idx >= SEQ * 64) return;
        int j = idx & 63, s = idx >> 6;
        double dfreq = pow(10000.0, -(double)j / 64.0);
        float freq = (float)dfreq;
        float angle = (float)s * freq;
        double da = (double)angle;
        g_rcos[idx] = (float)cos(da);
        g_rsin[idx] = (float)sin(da);
        return;
    }
    int idx = blockIdx.x * 256 + threadIdx.x;
    if (idx < NCOLS) {
        float b;
        if      (idx < 2048) b = bQ[idx];
        else if (idx < 2560) b = bK[idx - 2048];
        else                 b = bV[idx - 2560];
        g_bcat[idx] = b;
    }
    int n = idx >> 11;
    int k = idx & 2047;
    float v;
    if (n < 2048) {
        int head = n >> 7, h = n & 127;
        v = WQ[((size_t)head * KDIM + k) * DHEAD + h];
    } else if (n < 2560) {
        int head = (n - 2048) >> 7, h = n & 127;
        v = WK[((size_t)head * KDIM + k) * DHEAD + h];
    } else {
        int head = (n - 2560) >> 7, h = n & 127;
        v = WV[((size_t)head * KDIM + k) * DHEAD + h];
    }
    g_Wthi[idx] = __float2half_rn(v);
}

__global__ void repack_wo(const float* __restrict__ WO) {
    int idx = blockIdx.x * blockDim.x + threadIdx.x;
    if (idx >= DMODEL * KDIM) return;
    int k = idx >> 11;
    int m = idx & 2047;
    g_WOthi[(size_t)m * KDIM + k] = __float2half_rn(WO[idx]);
}

__global__ void split_f32h(const float* __restrict__ src, __half* __restrict__ hi,
                           __half* __restrict__ lo, int n) {
    int i = blockIdx.x * blockDim.x + threadIdx.x;
    if (i >= n) return;
    __half h, l;
    split1h(src[i], h, l);
    hi[i] = h;
    lo[i] = l;
}

// ---------------- mma.sync fp16 GEMM: A (hi+lo fp16) x W^T (fp16 single), 2 MMAs ----------------
// EPI=0: C = A*B^T + bias. EPI=1: fused QKV epilogue (rotary + splits + layouts).
#define BM 128
#define BN 128
#define BKT 64
#define MATB 16384
#define BUFB (3 * MATB)        // Ahi|Alo|Bh = 48 KB per stage
#define GSMEM (2 * BUFB)       // 96 KB
#define NSTG (KDIM / BKT)      // 32

__device__ __forceinline__ void load_stage(uint32_t bb, int k0, int m0, int n0, int tid,
                                           const __half* Ahi, const __half* Alo,
                                           const __half* Bh) {
    #pragma unroll
    for (int i = 0; i < 4; i++) {
        int c = tid + i * 256;
        int r = c >> 3, ch = c & 7;
        uint32_t so = bb + SWZ(r * 128 + ch * 16);
        size_t ga = (size_t)(m0 + r) * KDIM + k0 + ch * 8;
        size_t gb = (size_t)(n0 + r) * KDIM + k0 + ch * 8;
        cp16(so,            Ahi + ga);
        cp16(so + MATB,     Alo + ga);
        cp16(so + 2 * MATB, Bh + gb);
    }
}

template<int EPI>
__global__ __launch_bounds__(256, 1) void gemm3(
    const __half* __restrict__ Ahi, const __half* __restrict__ Alo,
    const __half* __restrict__ Bh,
    const float* __restrict__ bias, float* __restrict__ C, int N)
{
    extern __shared__ char sm[];
    const uint32_t smb = smem_u32(sm);
    const int tid = threadIdx.x;
    const int wid = tid >> 5, lid = tid & 31;
    const int m0 = blockIdx.x * BM, n0 = blockIdx.y * BN;
    const int wm = (wid & 1) * 64;
    const int wn = (wid >> 1) * 32;

    float acc[4][4][4];
    #pragma unroll
    for (int i = 0; i < 4; i++)
        #pragma unroll
        for (int j = 0; j < 4; j++)
            #pragma unroll
            for (int k = 0; k < 4; k++) acc[i][j][k] = 0.f;

    const int arow = lid & 15;
    const int asel = (lid >> 4) * 16;
    const int brow = ((lid >> 4) << 3) + (lid & 7);
    const int bsel = ((lid >> 3) & 1) * 16;

    load_stage(smb, 0, m0, n0, tid, Ahi, Alo, Bh);
    CP_COMMIT();

    for (int s = 0; s < NSTG; s++) {
        if (s + 1 < NSTG) {
            load_stage(smb + ((s + 1) & 1) * BUFB, (s + 1) * BKT, m0, n0, tid,
                       Ahi, Alo, Bh);
            CP_COMMIT();
            asm volatile("cp.async.wait_group 1;" ::: "memory");
        } else {
            asm volatile("cp.async.wait_group 0;" ::: "memory");
        }
        __syncthreads();

        uint32_t bb = smb + (s & 1) * BUFB;
        #pragma unroll
        for (int kk = 0; kk < 4; kk++) {
            uint32_t ah[4][4], al[4][4];
            #pragma unroll
            for (int ms = 0; ms < 4; ms++) {
                uint32_t off = SWZ((wm + ms * 16 + arow) * 128 + kk * 32 + asel);
                ldsm4(ah[ms], bb + off);
                ldsm4(al[ms], bb + MATB + off);
            }
            uint32_t bh[2][4];
            #pragma unroll
            for (int ns = 0; ns < 2; ns++) {
                uint32_t off = SWZ((wn + ns * 16 + brow) * 128 + kk * 32 + bsel);
                ldsm4(bh[ns], bb + 2 * MATB + off);
            }
            #pragma unroll
            for (int ms = 0; ms < 4; ms++)
                #pragma unroll
                for (int n8 = 0; n8 < 4; n8++) {
                    const uint32_t* ph = &bh[n8 >> 1][(n8 & 1) * 2];
                    mma_f16(acc[ms][n8], ah[ms], ph);
                    mma_f16(acc[ms][n8], al[ms], ph);
                }
        }
        __syncthreads();
    }

    const int erow = lid >> 2, ecol = (lid & 3) * 2;
    #pragma unroll
    for (int ms = 0; ms < 4; ms++) {
        int r0 = m0 + wm + ms * 16 + erow;
        #pragma unroll
        for (int n8 = 0; n8 < 4; n8++) {
            int c = n0 + wn + n8 * 8 + ecol;
            float2 bv = *(const float2*)&bias[c];
            float a00 = acc[ms][n8][0] + bv.x, a01 = acc[ms][n8][1] + bv.y;
            float a10 = acc[ms][n8][2] + bv.x, a11 = acc[ms][n8][3] + bv.y;
            if (EPI == 0) {
                *(float2*)&C[(size_t)r0 * N + c]       = make_float2(a00, a01);
                *(float2*)&C[(size_t)(r0 + 8) * N + c] = make_float2(a10, a11);
            } else {
                if (n0 < 2048) {                       // Q: rotary + bf16 split
                    int j = (c & 127) >> 1;
                    float c0 = g_rcos[r0 * 64 + j],       s0 = g_rsin[r0 * 64 + j];
                    float c1 = g_rcos[(r0 + 8) * 64 + j], s1 = g_rsin[(r0 + 8) * 64 + j];
                    store_pair(g_qbhi, g_qblo, (size_t)r0 * DMODEL + c,
                               a00 * c0 - a01 * s0, a00 * s0 + a01 * c0);
                    store_pair(g_qbhi, g_qblo, (size_t)(r0 + 8) * DMODEL + c,
                               a10 * c1 - a11 * s1, a10 * s1 + a11 * c1);
                } else if (n0 < 2560) {                // K: rotary + bf16 split, [kvh][s][dh]
                    int kvh = (c - 2048) >> 7, dh = c & 127, j = dh >> 1;
                    float c0 = g_rcos[r0 * 64 + j],       s0 = g_rsin[r0 * 64 + j];
                    float c1 = g_rcos[(r0 + 8) * 64 + j], s1 = g_rsin[(r0 + 8) * 64 + j];
                    size_t base = ((size_t)kvh * SEQ + r0) * DHEAD + dh;
                    store_pair(g_kbhi, g_kblo, base,
                               a00 * c0 - a01 * s0, a00 * s0 + a01 * c0);
                    store_pair(g_kbhi, g_kblo, base + 8 * DHEAD,
                               a10 * c1 - a11 * s1, a10 * s1 + a11 * c1);
                } else {                               // V: fp16 single + transpose [kvh][dh][s]
                    int kvh = (c - 2560) >> 7, dh = c & 127;
                    size_t b0 = ((size_t)kvh * DHEAD + dh) * SEQ;
                    size_t b1 = b0 + SEQ;
                    g_vthi[b0 + r0]     = __float2half_rn(a00);
                    g_vthi[b1 + r0]     = __float2half_rn(a01);
                    g_vthi[b0 + r0 + 8] = __float2half_rn(a10);
                    g_vthi[b1 + r0 + 8] = __float2half_rn(a11);
                }
            }
        }
    }
}

// ---------------- flash attention (Q smem bf16x2; S bf16x3; PV fp16 single-V) ----------------
// smem: Q 64KB | K 2x32KB | V 2x16KB = 160KB
#define SMQ 0
#define SMK 65536
#define SMV 131072
#define ATT_SMEM 163840

__device__ __forceinline__ void load_kv_stage(uint32_t smb, int buf, int kv0, int tid,
                                              const __nv_bfloat16* khi, const __nv_bfloat16* klo,
                                              const __half* vhi) {
    #pragma unroll
    for (int sb = 0; sb < 4; sb++) {
        int isl = sb >> 1, b = sb & 1;
        const __nv_bfloat16* src = isl ? klo : khi;
        #pragma unroll
        for (int i = 0; i < 2; i++) {
            int c = tid + i * 256;
            int r = c >> 3, ch = c & 7;
            cp16(smb + SMK + buf * 32768 + sb * 8192 + SWZ(r * 128 + ch * 16),
                 src + (size_t)(kv0 + r) * DHEAD + b * 64 + ch * 8);
        }
    }
    #pragma unroll
    for (int i = 0; i < 4; i++) {
        int c = tid + i * 256;
        int d = c >> 3, ch = c & 7;
        cp16(smb + SMV + buf * 16384 + SWZ(d * 128 + ch * 16),
             vhi + (size_t)d * SEQ + kv0 + ch * 8);
    }
}

__global__ __launch_bounds__(256, 1) void attn_mma() {
    extern __shared__ char sm[];
    const uint32_t smb = smem_u32(sm);
    const int tid = threadIdx.x;
    const int wid = tid >> 5, lid = tid & 31;
    const int qb = (int)(gridDim.x - 1) - (int)blockIdx.x;
    const int h = blockIdx.y;
    const int kvh = h >> 2;
    const int q0 = qb * 128;
    const int nkv = 2 * qb + 2;
    const int w16 = wid * 16;

    const int arow = lid & 15;
    const int asel = (lid >> 4) * 16;
    const int brow = ((lid >> 4) << 3) + (lid & 7);
    const int bsel = ((lid >> 3) & 1) * 16;

    const __nv_bfloat16* khi = g_kbhi + (size_t)kvh * SEQ * DHEAD;
    const __nv_bfloat16* klo = g_kblo + (size_t)kvh * SEQ * DHEAD;
    const __half* vhi = g_vthi + (size_t)kvh * DHEAD * SEQ;

    // prologue: Q tile (once) + KV stage 0
    #pragma unroll
    for (int sb = 0; sb < 4; sb++) {
        int isl = sb >> 1, b = sb & 1;
        const __nv_bfloat16* src = isl ? g_qblo : g_qbhi;
        #pragma unroll
        for (int i = 0; i < 4; i++) {
            int c = tid + i * 256;
            int r = c >> 3, ch = c & 7;
            cp16(smb + SMQ + sb * 16384 + SWZ(r * 128 + ch * 16),
                 src + (size_t)(q0 + r) * DMODEL + h * DHEAD + b * 64 + ch * 8);
        }
    }
    load_kv_stage(smb, 0, 0, tid, khi, klo, vhi);
    CP_COMMIT();

    float oacc[16][4];
    #pragma unroll
    for (int i = 0; i < 16; i++)
        #pragma unroll
        for (int j = 0; j < 4; j++) oacc[i][j] = 0.f;
    float m2[2] = {-1e30f, -1e30f};
    float l2[2] = {0.f, 0.f};
    const float KE = (float)(1.4426950408889634 / 11.313708498984761);

    for (int kb = 0; kb < nkv; kb++) {
        if (kb + 1 < nkv) {
            load_kv_stage(smb, (kb + 1) & 1, (kb + 1) * 64, tid, khi, klo, vhi);
            CP_COMMIT();
            asm volatile("cp.async.wait_group 1;" ::: "memory");
        } else {
            asm volatile("cp.async.wait_group 0;" ::: "memory");
        }
        __syncthreads();

        const uint32_t kbase = smb + SMK + (kb & 1) * 32768;
        const uint32_t vbase = smb + SMV + (kb & 1) * 16384;

        // ---- S = Q K^T (bf16x3) ----
        float sacc[8][4];
        #pragma unroll
        for (int i = 0; i < 8; i++)
            #pragma unroll
            for (int j = 0; j < 4; j++) sacc[i][j] = 0.f;

        #pragma unroll
        for (int kk = 0; kk < 8; kk++) {
            int b = kk >> 2, koff = (kk & 3) * 32;
            uint32_t ah[4], al[4];
            uint32_t qoff = smb + SMQ + b * 16384 + SWZ((w16 + arow) * 128 + koff + asel);
            ldsm4(ah, qoff);
            ldsm4(al, qoff + 32768);
            #pragma unroll
            for (int ns = 0; ns < 4; ns++) {
                uint32_t bh[4], bl[4];
                uint32_t boff = kbase + b * 8192 + SWZ((ns * 16 + brow) * 128 + koff + bsel);
                ldsm4(bh, boff);
                ldsm4(bl, boff + 16384);
                mma_bf16(sacc[2 * ns],     ah, bh);     mma_bf16(sacc[2 * ns],     ah, bl);     mma_bf16(sacc[2 * ns],     al, bh);
                mma_bf16(sacc[2 * ns + 1], ah, bh + 2); mma_bf16(sacc[2 * ns + 1], ah, bl + 2); mma_bf16(sacc[2 * ns + 1], al, bh + 2);
            }
        }

        // ---- online softmax ----
        const int kv0 = kb * 64;
        const bool dodiag = (kb >= nkv - 2);
        #pragma unroll
        for (int g = 0; g < 2; g++) {
            int grow = q0 + w16 + (lid >> 2) + g * 8;
            if (dodiag) {
                #pragma unroll
                for (int n8 = 0; n8 < 8; n8++) {
                    int col = kv0 + n8 * 8 + (lid & 3) * 2;
                    if (col > grow)     sacc[n8][2 * g]     = -1e30f;
                    if (col + 1 > grow) sacc[n8][2 * g + 1] = -1e30f;
                }
            }
            float mt = -1e30f;
            #pragma unroll
            for (int n8 = 0; n8 < 8; n8++)
                mt = fmaxf(mt, fmaxf(sacc[n8][2 * g], sacc[n8][2 * g + 1]));
            mt = fmaxf(mt, __shfl_xor_sync(0xffffffffu, mt, 1));
            mt = fmaxf(mt, __shfl_xor_sync(0xffffffffu, mt, 2));
            float mnew = fmaxf(m2[g], mt);
            float alpha = ex2f((m2[g] - mnew) * KE);
            float ls = 0.f;
            #pragma unroll
            for (int n8 = 0; n8 < 8; n8++) {
                float p0 = ex2f((sacc[n8][2 * g]     - mnew) * KE);
                float p1 = ex2f((sacc[n8][2 * g + 1] - mnew) * KE);
                sacc[n8][2 * g] = p0; sacc[n8][2 * g + 1] = p1;
                ls += p0 + p1;
            }
            ls += __shfl_xor_sync(0xffffffffu, ls, 1);
            ls += __shfl_xor_sync(0xffffffffu, ls, 2);
            l2[g] = l2[g] * alpha + ls;
            m2[g] = mnew;
            #pragma unroll
            for (int t = 0; t < 16; t++) {
                oacc[t][2 * g]     *= alpha;
                oacc[t][2 * g + 1] *= alpha;
            }
        }

        // ---- O += P V  (P fp16, V fp16 single: 1 MMA per n8 tile) ----
        #pragma unroll
        for (int t = 0; t < 4; t++) {
            uint32_t pa[4];
            pa[0] = f16x2(sacc[2 * t][0],     sacc[2 * t][1]);
            pa[1] = f16x2(sacc[2 * t][2],     sacc[2 * t][3]);
            pa[2] = f16x2(sacc[2 * t + 1][0], sacc[2 * t + 1][1]);
            pa[3] = f16x2(sacc[2 * t + 1][2], sacc[2 * t + 1][3]);
            #pragma unroll
            for (int ns = 0; ns < 8; ns++) {
                uint32_t vh[4];
                ldsm4(vh, vbase + SWZ((ns * 16 + brow) * 128 + t * 32 + bsel));
                mma_f16(oacc[2 * ns],     pa, vh);
                mma_f16(oacc[2 * ns + 1], pa, vh + 2);
            }
        }
        __syncthreads();
    }

    // ---- epilogue: z as fp16 hi/lo ----
    float inv0 = 1.f / l2[0], inv1 = 1.f / l2[1];
    int r0 = q0 + w16 + (lid >> 2);
    int cb = h * DHEAD + (lid & 3) * 2;
    #pragma unroll
    for (int n8 = 0; n8 < 16; n8++) {
        int col = cb + n8 * 8;
        store_pair_h(g_zhi, g_zlo, (size_t)r0 * DMODEL + col,
                     oacc[n8][0] * inv0, oacc[n8][1] * inv0);
        store_pair_h(g_zhi, g_zlo, (size_t)(r0 + 8) * DMODEL + col,
                     oacc[n8][2] * inv1, oacc[n8][3] * inv1);
    }
}

// ---------------- launcher ----------------
extern "C" void kernel_launch(void* const* d_in, const int* in_sizes, int n_in,
                              void* d_out, int out_size) {
    const float* x  = (const float*)d_in[0];
    const float* WQ = (const float*)d_in[1];
    const float* WK = (const float*)d_in[2];
    const float* WV = (const float*)d_in[3];
    const float* WO = (const float*)d_in[4];
    const float* bQ = (const float*)d_in[5];
    const float* bK = (const float*)d_in[6];
    const float* bV = (const float*)d_in[7];
    const float* bO = (const float*)d_in[8];
    float* out = (float*)d_out;

    float* bcat;
    __half *xhi, *xlo, *zhi, *zlo, *Wthi, *WOthi;
    cudaGetSymbolAddress((void**)&bcat,  g_bcat);
    cudaGetSymbolAddress((void**)&xhi,   g_xhi);
    cudaGetSymbolAddress((void**)&xlo,   g_xlo);
    cudaGetSymbolAddress((void**)&zhi,   g_zhi);
    cudaGetSymbolAddress((void**)&zlo,   g_zlo);
    cudaGetSymbolAddress((void**)&Wthi,  g_Wthi);
    cudaGetSymbolAddress((void**)&WOthi, g_WOthi);

    cudaFuncSetAttribute(gemm3<0>, cudaFuncAttributeMaxDynamicSharedMemorySize, GSMEM);
    cudaFuncSetAttribute(gemm3<1>, cudaFuncAttributeMaxDynamicSharedMemorySize, GSMEM);
    cudaFuncSetAttribute(attn_mma, cudaFuncAttributeMaxDynamicSharedMemorySize, ATT_SMEM);

    // 1) weight repacks (+rotary table) + input split
    repack_wqkv_rot<<<REP_BLOCKS + (SEQ * 64) / 256, 256>>>(WQ, WK, WV, bQ, bK, bV);
    repack_wo<<<(DMODEL * KDIM + 255) / 256, 256>>>(WO);
    split_f32h<<<(SEQ * DMODEL + 255) / 256, 256>>>(x, xhi, xlo, SEQ * DMODEL);

    // 2) QKV projection + fused bias/rotary/split/layout epilogue
    {
        dim3 grid(SEQ / BM, NCOLS / BN);
        gemm3<1><<<grid, 256, GSMEM>>>(xhi, xlo, Wthi, bcat, nullptr, NCOLS);
    }
    // 3) causal flash attention -> zhi/zlo
    {
        dim3 grid(SEQ / 128, NH);
        attn_mma<<<grid, 256, ATT_SMEM>>>();
    }
    // 4) O-projection
    {
        dim3 grid(SEQ / BM, DMODEL / BN);
        gemm3<0><<<grid, 256, GSMEM>>>(zhi, zlo, WOthi, bO, out, DMODEL);
    }
}

// round 9
// speedup vs baseline: 1.6663x; 1.1973x over previous
#include <cuda_runtime.h>
#include <cuda_bf16.h>
#include <cuda_fp16.h>
#include <math.h>
#include <stdint.h>

#define SEQ     4096
#define DMODEL  2048
#define DHEAD   128
#define NH      16
#define NKV     4
#define NCOLS   3072
#define KDIM    2048

// ---------------- scratch ----------------
__device__ __align__(256) float g_bcat[NCOLS];
__device__ __align__(256) __half g_xhi[SEQ * DMODEL];      // x fp16 hi/lo split
__device__ __align__(256) __half g_xlo[SEQ * DMODEL];
__device__ __align__(256) __half g_zhi[SEQ * DMODEL];      // z fp16 hi/lo split
__device__ __align__(256) __half g_zlo[SEQ * DMODEL];
__device__ __align__(256) __half g_Wthi[NCOLS * KDIM];     // QKV W^T fp16 single
__device__ __align__(256) __half g_WOthi[DMODEL * KDIM];   // W_O^T fp16 single
__device__ __align__(256) __half g_qbhi[SEQ * DMODEL];     // Q fp16 hi/lo split
__device__ __align__(256) __half g_qblo[SEQ * DMODEL];
__device__ __align__(256) __half g_kh[NKV * SEQ * DHEAD];  // K fp16 single
__device__ __align__(256) __half g_vthi[NKV * DHEAD * SEQ];// V^T fp16 single
__device__ __align__(256) float g_rcos[SEQ * 64];
__device__ __align__(256) float g_rsin[SEQ * 64];

// ---------------- helpers ----------------
__device__ __forceinline__ uint32_t smem_u32(const void* p) {
    uint32_t a;
    asm("{ .reg .u64 t; cvta.to.shared.u64 t, %1; cvt.u32.u64 %0, t; }" : "=r"(a) : "l"(p));
    return a;
}
__device__ __forceinline__ void cp16(uint32_t s, const void* g) {
    asm volatile("cp.async.cg.shared.global [%0], [%1], 16;" :: "r"(s), "l"(g));
}
#define CP_COMMIT() asm volatile("cp.async.commit_group;" ::: "memory")
__device__ __forceinline__ void ldsm4(uint32_t* r, uint32_t addr) {
    asm volatile("ldmatrix.sync.aligned.m8n8.x4.shared.b16 {%0,%1,%2,%3}, [%4];"
        : "=r"(r[0]), "=r"(r[1]), "=r"(r[2]), "=r"(r[3]) : "r"(addr));
}
__device__ __forceinline__ void mma_f16(float* d, const uint32_t* a, const uint32_t* b) {
    asm volatile("mma.sync.aligned.m16n8k16.row.col.f32.f16.f16.f32 "
        "{%0,%1,%2,%3}, {%4,%5,%6,%7}, {%8,%9}, {%0,%1,%2,%3};"
        : "+f"(d[0]), "+f"(d[1]), "+f"(d[2]), "+f"(d[3])
        : "r"(a[0]), "r"(a[1]), "r"(a[2]), "r"(a[3]), "r"(b[0]), "r"(b[1]));
}
__device__ __forceinline__ float ex2f(float x) {
    float y; asm("ex2.approx.ftz.f32 %0, %1;" : "=f"(y) : "f"(x)); return y;
}
// pack (p0 -> lo16, p1 -> hi16) as fp16x2
__device__ __forceinline__ uint32_t f16x2(float p0, float p1) {
    uint32_t r;
    asm("cvt.rn.f16x2.f32 %0, %1, %2;" : "=r"(r) : "f"(p1), "f"(p0));
    return r;
}
__device__ __forceinline__ void split1h(float v, __half& h, __half& l) {
    h = __float2half_rn(v);
    l = __float2half_rn(v - __half2float(h));
}
__device__ __forceinline__ void store_pair_h(__half* hi, __half* lo,
                                             size_t off, float v0, float v1) {
    __half h0, l0, h1, l1;
    split1h(v0, h0, l0);
    split1h(v1, h1, l1);
    *(__half2*)(hi + off) = __half2(h0, h1);
    *(__half2*)(lo + off) = __half2(l0, l1);
}
__device__ __forceinline__ void store1h(__half* dst, size_t off, float v0, float v1) {
    *(__half2*)(dst + off) = __half2(__float2half_rn(v0), __float2half_rn(v1));
}
#define SWZ(off) ((off) ^ (((off) >> 3) & 0x70))

// ---------------- repack QKV weights (smem transpose) + rotary table + bias ----------------
// grid.x = 6144 transpose blocks + 1024 rotab blocks + 12 bias blocks
#define TBLK_QKV 6144   // 24 heads x (64 ktiles x 4 htiles)
#define ROTB 1024
__global__ void repack_wqkv_rot(const float* __restrict__ WQ, const float* __restrict__ WK,
                                const float* __restrict__ WV, const float* __restrict__ bQ,
                                const float* __restrict__ bK, const float* __restrict__ bV) {
    int b = blockIdx.x;
    int tid = threadIdx.x;
    if (b >= TBLK_QKV + ROTB) {                 // bias
        int idx = (b - TBLK_QKV - ROTB) * 256 + tid;
        if (idx >= NCOLS) return;
        float v;
        if      (idx < 2048) v = bQ[idx];
        else if (idx < 2560) v = bK[idx - 2048];
        else                 v = bV[idx - 2560];
        g_bcat[idx] = v;
        return;
    }
    if (b >= TBLK_QKV) {                        // rotary table
        int idx = (b - TBLK_QKV) * 256 + tid;
        int j = idx & 63, s = idx >> 6;
        double dfreq = pow(10000.0, -(double)j / 64.0);
        float freq = (float)dfreq;
        float angle = (float)s * freq;
        double da = (double)angle;
        g_rcos[idx] = (float)cos(da);
        g_rsin[idx] = (float)sin(da);
        return;
    }
    // transpose: head H in 0..23 (0-15 Q, 16-19 K, 20-23 V); per-head (k,h) -> (h,k)
    __shared__ float tile[32][33];
    int H = b >> 8;
    int rem = b & 255;
    int k0 = (rem >> 2) * 32;
    int h0 = (rem & 3) * 32;
    const float* src;
    int nbase;
    if (H < 16)      { src = WQ + (size_t)H * KDIM * DHEAD;        nbase = H * 128; }
    else if (H < 20) { src = WK + (size_t)(H - 16) * KDIM * DHEAD; nbase = 2048 + (H - 16) * 128; }
    else             { src = WV + (size_t)(H - 20) * KDIM * DHEAD; nbase = 2560 + (H - 20) * 128; }
    int c = tid & 31, r0t = tid >> 5;
    #pragma unroll
    for (int p = 0; p < 4; p++) {
        int r = r0t + p * 8;
        tile[r][c] = src[(size_t)(k0 + r) * DHEAD + h0 + c];
    }
    __syncthreads();
    #pragma unroll
    for (int p = 0; p < 4; p++) {
        int rr = r0t + p * 8;
        g_Wthi[(size_t)(nbase + h0 + rr) * KDIM + k0 + c] = __float2half_rn(tile[c][rr]);
    }
}

// W_O transpose: src [2048 nh][2048 m] -> dest [m][nh]; grid (64,64)
__global__ void repack_wo(const float* __restrict__ WO) {
    __shared__ float tile[32][33];
    int n0 = blockIdx.x * 32;
    int m0 = blockIdx.y * 32;
    int tid = threadIdx.x;
    int c = tid & 31, r0t = tid >> 5;
    #pragma unroll
    for (int p = 0; p < 4; p++) {
        int r = r0t + p * 8;
        tile[r][c] = WO[(size_t)(n0 + r) * DMODEL + m0 + c];
    }
    __syncthreads();
    #pragma unroll
    for (int p = 0; p < 4; p++) {
        int rr = r0t + p * 8;
        g_WOthi[(size_t)(m0 + rr) * KDIM + n0 + c] = __float2half_rn(tile[c][rr]);
    }
}

__global__ void split_f32h(const float* __restrict__ src, __half* __restrict__ hi,
                           __half* __restrict__ lo, int n) {
    int i = blockIdx.x * blockDim.x + threadIdx.x;
    if (i >= n) return;
    __half h, l;
    split1h(src[i], h, l);
    hi[i] = h;
    lo[i] = l;
}

// ---------------- mma.sync fp16 GEMM: A (hi+lo fp16) x W^T (fp16 single), 2 CTA/SM ----------------
#define BM 128
#define BN 128
#define BKT 64
#define MATB 16384
#define BUFB (3 * MATB)        // Ahi|Alo|Bh = 48 KB per stage
#define GSMEM (2 * BUFB)       // 96 KB
#define NSTG (KDIM / BKT)      // 32

__device__ __forceinline__ void load_stage(uint32_t bb, int k0, int m0, int n0, int tid,
                                           const __half* Ahi, const __half* Alo,
                                           const __half* Bh) {
    #pragma unroll
    for (int i = 0; i < 4; i++) {
        int c = tid + i * 256;
        int r = c >> 3, ch = c & 7;
        uint32_t so = bb + SWZ(r * 128 + ch * 16);
        size_t ga = (size_t)(m0 + r) * KDIM + k0 + ch * 8;
        size_t gb = (size_t)(n0 + r) * KDIM + k0 + ch * 8;
        cp16(so,            Ahi + ga);
        cp16(so + MATB,     Alo + ga);
        cp16(so + 2 * MATB, Bh + gb);
    }
}

template<int EPI>
__global__ __launch_bounds__(256, 2) void gemm3(
    const __half* __restrict__ Ahi, const __half* __restrict__ Alo,
    const __half* __restrict__ Bh,
    const float* __restrict__ bias, float* __restrict__ C, int N)
{
    extern __shared__ char sm[];
    const uint32_t smb = smem_u32(sm);
    const int tid = threadIdx.x;
    const int wid = tid >> 5, lid = tid & 31;
    const int m0 = blockIdx.x * BM, n0 = blockIdx.y * BN;
    const int wm = (wid & 1) * 64;
    const int wn = (wid >> 1) * 32;

    float acc[4][4][4];
    #pragma unroll
    for (int i = 0; i < 4; i++)
        #pragma unroll
        for (int j = 0; j < 4; j++)
            #pragma unroll
            for (int k = 0; k < 4; k++) acc[i][j][k] = 0.f;

    const int arow = lid & 15;
    const int asel = (lid >> 4) * 16;
    const int brow = ((lid >> 4) << 3) + (lid & 7);
    const int bsel = ((lid >> 3) & 1) * 16;

    load_stage(smb, 0, m0, n0, tid, Ahi, Alo, Bh);
    CP_COMMIT();

    for (int s = 0; s < NSTG; s++) {
        if (s + 1 < NSTG) {
            load_stage(smb + ((s + 1) & 1) * BUFB, (s + 1) * BKT, m0, n0, tid,
                       Ahi, Alo, Bh);
            CP_COMMIT();
            asm volatile("cp.async.wait_group 1;" ::: "memory");
        } else {
            asm volatile("cp.async.wait_group 0;" ::: "memory");
        }
        __syncthreads();

        uint32_t bb = smb + (s & 1) * BUFB;
        #pragma unroll
        for (int kk = 0; kk < 4; kk++) {
            uint32_t ah[4][4], al[4][4];
            #pragma unroll
            for (int ms = 0; ms < 4; ms++) {
                uint32_t off = SWZ((wm + ms * 16 + arow) * 128 + kk * 32 + asel);
                ldsm4(ah[ms], bb + off);
                ldsm4(al[ms], bb + MATB + off);
            }
            uint32_t bh[2][4];
            #pragma unroll
            for (int ns = 0; ns < 2; ns++) {
                uint32_t off = SWZ((wn + ns * 16 + brow) * 128 + kk * 32 + bsel);
                ldsm4(bh[ns], bb + 2 * MATB + off);
            }
            #pragma unroll
            for (int ms = 0; ms < 4; ms++)
                #pragma unroll
                for (int n8 = 0; n8 < 4; n8++) {
                    const uint32_t* ph = &bh[n8 >> 1][(n8 & 1) * 2];
                    mma_f16(acc[ms][n8], ah[ms], ph);
                    mma_f16(acc[ms][n8], al[ms], ph);
                }
        }
        __syncthreads();
    }

    const int erow = lid >> 2, ecol = (lid & 3) * 2;
    #pragma unroll
    for (int ms = 0; ms < 4; ms++) {
        int r0 = m0 + wm + ms * 16 + erow;
        #pragma unroll
        for (int n8 = 0; n8 < 4; n8++) {
            int c = n0 + wn + n8 * 8 + ecol;
            float2 bv = *(const float2*)&bias[c];
            float a00 = acc[ms][n8][0] + bv.x, a01 = acc[ms][n8][1] + bv.y;
            float a10 = acc[ms][n8][2] + bv.x, a11 = acc[ms][n8][3] + bv.y;
            if (EPI == 0) {
                *(float2*)&C[(size_t)r0 * N + c]       = make_float2(a00, a01);
                *(float2*)&C[(size_t)(r0 + 8) * N + c] = make_float2(a10, a11);
            } else {
                if (n0 < 2048) {                       // Q: rotary + fp16 split
                    int j = (c & 127) >> 1;
                    float c0 = g_rcos[r0 * 64 + j],       s0 = g_rsin[r0 * 64 + j];
                    float c1 = g_rcos[(r0 + 8) * 64 + j], s1 = g_rsin[(r0 + 8) * 64 + j];
                    store_pair_h(g_qbhi, g_qblo, (size_t)r0 * DMODEL + c,
                                 a00 * c0 - a01 * s0, a00 * s0 + a01 * c0);
                    store_pair_h(g_qbhi, g_qblo, (size_t)(r0 + 8) * DMODEL + c,
                                 a10 * c1 - a11 * s1, a10 * s1 + a11 * c1);
                } else if (n0 < 2560) {                // K: rotary + fp16 single, [kvh][s][dh]
                    int kvh = (c - 2048) >> 7, dh = c & 127, j = dh >> 1;
                    float c0 = g_rcos[r0 * 64 + j],       s0 = g_rsin[r0 * 64 + j];
                    float c1 = g_rcos[(r0 + 8) * 64 + j], s1 = g_rsin[(r0 + 8) * 64 + j];
                    size_t base = ((size_t)kvh * SEQ + r0) * DHEAD + dh;
                    store1h(g_kh, base,
                            a00 * c0 - a01 * s0, a00 * s0 + a01 * c0);
                    store1h(g_kh, base + 8 * DHEAD,
                            a10 * c1 - a11 * s1, a10 * s1 + a11 * c1);
                } else {                               // V: fp16 single + transpose [kvh][dh][s]
                    int kvh = (c - 2560) >> 7, dh = c & 127;
                    size_t b0 = ((size_t)kvh * DHEAD + dh) * SEQ;
                    size_t b1 = b0 + SEQ;
                    g_vthi[b0 + r0]     = __float2half_rn(a00);
                    g_vthi[b1 + r0]     = __float2half_rn(a01);
                    g_vthi[b0 + r0 + 8] = __float2half_rn(a10);
                    g_vthi[b1 + r0 + 8] = __float2half_rn(a11);
                }
            }
        }
    }
}

// ---------------- flash attention (S: fp16 Qhi+Qlo x K-single; PV: fp16 single) ----------------
// smem: Q 64KB (4 planes 16KB) | K 2x16KB | V 2x16KB = 128KB
#define SMK 65536
#define SMV 98304
#define ATT_SMEM 131072

__device__ __forceinline__ void load_kv_stage(uint32_t smb, int buf, int kv0, int tid,
                                              const __half* kh, const __half* vhi) {
    #pragma unroll
    for (int sb = 0; sb < 2; sb++) {
        #pragma unroll
        for (int i = 0; i < 2; i++) {
            int c = tid + i * 256;
            int r = c >> 3, ch = c & 7;
            cp16(smb + SMK + buf * 16384 + sb * 8192 + SWZ(r * 128 + ch * 16),
                 kh + (size_t)(kv0 + r) * DHEAD + sb * 64 + ch * 8);
        }
    }
    #pragma unroll
    for (int i = 0; i < 4; i++) {
        int c = tid + i * 256;
        int d = c >> 3, ch = c & 7;
        cp16(smb + SMV + buf * 16384 + SWZ(d * 128 + ch * 16),
             vhi + (size_t)d * SEQ + kv0 + ch * 8);
    }
}

__global__ __launch_bounds__(256, 1) void attn_mma() {
    extern __shared__ char sm[];
    const uint32_t smb = smem_u32(sm);
    const int tid = threadIdx.x;
    const int wid = tid >> 5, lid = tid & 31;
    const int qb = (int)(gridDim.x - 1) - (int)blockIdx.x;
    const int h = blockIdx.y;
    const int kvh = h >> 2;
    const int q0 = qb * 128;
    const int nkv = 2 * qb + 2;
    const int w16 = wid * 16;

    const int arow = lid & 15;
    const int asel = (lid >> 4) * 16;
    const int brow = ((lid >> 4) << 3) + (lid & 7);
    const int bsel = ((lid >> 3) & 1) * 16;

    const __half* kh  = g_kh + (size_t)kvh * SEQ * DHEAD;
    const __half* vhi = g_vthi + (size_t)kvh * DHEAD * SEQ;

    // prologue: Q tile (once: hi planes 0,1 + lo planes 2,3) + KV stage 0
    #pragma unroll
    for (int sb = 0; sb < 4; sb++) {
        int isl = sb >> 1, b = sb & 1;
        const __half* src = isl ? g_qblo : g_qbhi;
        #pragma unroll
        for (int i = 0; i < 4; i++) {
            int c = tid + i * 256;
            int r = c >> 3, ch = c & 7;
            cp16(smb + sb * 16384 + SWZ(r * 128 + ch * 16),
                 src + (size_t)(q0 + r) * DMODEL + h * DHEAD + b * 64 + ch * 8);
        }
    }
    load_kv_stage(smb, 0, 0, tid, kh, vhi);
    CP_COMMIT();

    float oacc[16][4];
    #pragma unroll
    for (int i = 0; i < 16; i++)
        #pragma unroll
        for (int j = 0; j < 4; j++) oacc[i][j] = 0.f;
    float m2[2] = {-1e30f, -1e30f};
    float l2[2] = {0.f, 0.f};
    const float KE = (float)(1.4426950408889634 / 11.313708498984761);

    for (int kb = 0; kb < nkv; kb++) {
        if (kb + 1 < nkv) {
            load_kv_stage(smb, (kb + 1) & 1, (kb + 1) * 64, tid, kh, vhi);
            CP_COMMIT();
            asm volatile("cp.async.wait_group 1;" ::: "memory");
        } else {
            asm volatile("cp.async.wait_group 0;" ::: "memory");
        }
        __syncthreads();

        const uint32_t kbase = smb + SMK + (kb & 1) * 16384;
        const uint32_t vbase = smb + SMV + (kb & 1) * 16384;

        // ---- S = Q K^T (fp16: Qhi*K + Qlo*K) ----
        float sacc[8][4];
        #pragma unroll
        for (int i = 0; i < 8; i++)
            #pragma unroll
            for (int j = 0; j < 4; j++) sacc[i][j] = 0.f;

        #pragma unroll
        for (int kk = 0; kk < 8; kk++) {
            int b = kk >> 2, koff = (kk & 3) * 32;
            uint32_t qh[4], ql[4];
            uint32_t qoff = smb + b * 16384 + SWZ((w16 + arow) * 128 + koff + asel);
            ldsm4(qh, qoff);
            ldsm4(ql, qoff + 32768);
            #pragma unroll
            for (int ns = 0; ns < 4; ns++) {
                uint32_t bk[4];
                ldsm4(bk, kbase + b * 8192 + SWZ((ns * 16 + brow) * 128 + koff + bsel));
                mma_f16(sacc[2 * ns],     qh, bk);     mma_f16(sacc[2 * ns],     ql, bk);
                mma_f16(sacc[2 * ns + 1], qh, bk + 2); mma_f16(sacc[2 * ns + 1], ql, bk + 2);
            }
        }

        // ---- online softmax ----
        const int kv0 = kb * 64;
        const bool dodiag = (kb >= nkv - 2);
        #pragma unroll
        for (int g = 0; g < 2; g++) {
            int grow = q0 + w16 + (lid >> 2) + g * 8;
            if (dodiag) {
                #pragma unroll
                for (int n8 = 0; n8 < 8; n8++) {
                    int col = kv0 + n8 * 8 + (lid & 3) * 2;
                    if (col > grow)     sacc[n8][2 * g]     = -1e30f;
                    if (col + 1 > grow) sacc[n8][2 * g + 1] = -1e30f;
                }
            }
            float mt = -1e30f;
            #pragma unroll
            for (int n8 = 0; n8 < 8; n8++)
                mt = fmaxf(mt, fmaxf(sacc[n8][2 * g], sacc[n8][2 * g + 1]));
            mt = fmaxf(mt, __shfl_xor_sync(0xffffffffu, mt, 1));
            mt = fmaxf(mt, __shfl_xor_sync(0xffffffffu, mt, 2));
            float mnew = fmaxf(m2[g], mt);
            float alpha = ex2f((m2[g] - mnew) * KE);
            float ls = 0.f;
            #pragma unroll
            for (int n8 = 0; n8 < 8; n8++) {
                float p0 = ex2f((sacc[n8][2 * g]     - mnew) * KE);
                float p1 = ex2f((sacc[n8][2 * g + 1] - mnew) * KE);
                sacc[n8][2 * g] = p0; sacc[n8][2 * g + 1] = p1;
                ls += p0 + p1;
            }
            ls += __shfl_xor_sync(0xffffffffu, ls, 1);
            ls += __shfl_xor_sync(0xffffffffu, ls, 2);
            l2[g] = l2[g] * alpha + ls;
            m2[g] = mnew;
            #pragma unroll
            for (int t = 0; t < 16; t++) {
                oacc[t][2 * g]     *= alpha;
                oacc[t][2 * g + 1] *= alpha;
            }
        }

        // ---- O += P V  (P fp16, V fp16 single) ----
        #pragma unroll
        for (int t = 0; t < 4; t++) {
            uint32_t pa[4];
            pa[0] = f16x2(sacc[2 * t][0],     sacc[2 * t][1]);
            pa[1] = f16x2(sacc[2 * t][2],     sacc[2 * t][3]);
            pa[2] = f16x2(sacc[2 * t + 1][0], sacc[2 * t + 1][1]);
            pa[3] = f16x2(sacc[2 * t + 1][2], sacc[2 * t + 1][3]);
            #pragma unroll
            for (int ns = 0; ns < 8; ns++) {
                uint32_t vh[4];
                ldsm4(vh, vbase + SWZ((ns * 16 + brow) * 128 + t * 32 + bsel));
                mma_f16(oacc[2 * ns],     pa, vh);
                mma_f16(oacc[2 * ns + 1], pa, vh + 2);
            }
        }
        __syncthreads();
    }

    // ---- epilogue: z as fp16 hi/lo ----
    float inv0 = 1.f / l2[0], inv1 = 1.f / l2[1];
    int r0 = q0 + w16 + (lid >> 2);
    int cb = h * DHEAD + (lid & 3) * 2;
    #pragma unroll
    for (int n8 = 0; n8 < 16; n8++) {
        int col = cb + n8 * 8;
        store_pair_h(g_zhi, g_zlo, (size_t)r0 * DMODEL + col,
                     oacc[n8][0] * inv0, oacc[n8][1] * inv0);
        store_pair_h(g_zhi, g_zlo, (size_t)(r0 + 8) * DMODEL + col,
                     oacc[n8][2] * inv1, oacc[n8][3] * inv1);
    }
}

// ---------------- launcher ----------------
extern "C" void kernel_launch(void* const* d_in, const int* in_sizes, int n_in,
                              void* d_out, int out_size) {
    const float* x  = (const float*)d_in[0];
    const float* WQ = (const float*)d_in[1];
    const float* WK = (const float*)d_in[2];
    const float* WV = (const float*)d_in[3];
    const float* WO = (const float*)d_in[4];
    const float* bQ = (const float*)d_in[5];
    const float* bK = (const float*)d_in[6];
    const float* bV = (const float*)d_in[7];
    const float* bO = (const float*)d_in[8];
    float* out = (float*)d_out;

    float* bcat;
    __half *xhi, *xlo, *zhi, *zlo, *Wthi, *WOthi;
    cudaGetSymbolAddress((void**)&bcat,  g_bcat);
    cudaGetSymbolAddress((void**)&xhi,   g_xhi);
    cudaGetSymbolAddress((void**)&xlo,   g_xlo);
    cudaGetSymbolAddress((void**)&zhi,   g_zhi);
    cudaGetSymbolAddress((void**)&zlo,   g_zlo);
    cudaGetSymbolAddress((void**)&Wthi,  g_Wthi);
    cudaGetSymbolAddress((void**)&WOthi, g_WOthi);

    cudaFuncSetAttribute(gemm3<0>, cudaFuncAttributeMaxDynamicSharedMemorySize, GSMEM);
    cudaFuncSetAttribute(gemm3<1>, cudaFuncAttributeMaxDynamicSharedMemorySize, GSMEM);
    cudaFuncSetAttribute(attn_mma, cudaFuncAttributeMaxDynamicSharedMemorySize, ATT_SMEM);

    // 1) weight repacks (coalesced transposes) + rotary table + bias + input split
    repack_wqkv_rot<<<TBLK_QKV + ROTB + 12, 256>>>(WQ, WK, WV, bQ, bK, bV);
    {
        dim3 grid(64, 64);
        repack_wo<<<grid, 256>>>(WO);
    }
    split_f32h<<<(SEQ * DMODEL + 255) / 256, 256>>>(x, xhi, xlo, SEQ * DMODEL);

    // 2) QKV projection + fused bias/rotary/split/layout epilogue
    {
        dim3 grid(SEQ / BM, NCOLS / BN);
        gemm3<1><<<grid, 256, GSMEM>>>(xhi, xlo, Wthi, bcat, nullptr, NCOLS);
    }
    // 3) causal flash attention -> zhi/zlo
    {
        dim3 grid(SEQ / 128, NH);
        attn_mma<<<grid, 256, ATT_SMEM>>>();
    }
    // 4) O-projection
    {
        dim3 grid(SEQ / BM, DMODEL / BN);
        gemm3<0><<<grid, 256, GSMEM>>>(zhi, zlo, WOthi, bO, out, DMODEL);
    }
}

// round 10
// speedup vs baseline: 2.2309x; 1.3388x over previous
#include <cuda_runtime.h>
#include <cuda_fp16.h>
#include <math.h>
#include <stdint.h>

#define SEQ     4096
#define DMODEL  2048
#define DHEAD   128
#define NH      16
#define NKV     4
#define NCOLS   3072
#define KDIM    2048

// ---------------- scratch ----------------
__device__ __align__(256) float g_bcat[NCOLS];
__device__ __align__(256) __half g_xh[SEQ * DMODEL];       // x fp16
__device__ __align__(256) __half g_zh[SEQ * DMODEL];       // z fp16
__device__ __align__(256) __half g_Wthi[NCOLS * KDIM];     // QKV W^T fp16
__device__ __align__(256) __half g_WOthi[DMODEL * KDIM];   // W_O^T fp16
__device__ __align__(256) __half g_qh[SEQ * DMODEL];       // Q fp16 (post-rotary)
__device__ __align__(256) __half g_kh[NKV * SEQ * DHEAD];  // K fp16 (post-rotary)
__device__ __align__(256) __half g_vthi[NKV * DHEAD * SEQ];// V^T fp16
__device__ __align__(256) float g_rcos[SEQ * 64];
__device__ __align__(256) float g_rsin[SEQ * 64];

// ---------------- helpers ----------------
__device__ __forceinline__ uint32_t smem_u32(const void* p) {
    uint32_t a;
    asm("{ .reg .u64 t; cvta.to.shared.u64 t, %1; cvt.u32.u64 %0, t; }" : "=r"(a) : "l"(p));
    return a;
}
__device__ __forceinline__ void cp16(uint32_t s, const void* g) {
    asm volatile("cp.async.cg.shared.global [%0], [%1], 16;" :: "r"(s), "l"(g));
}
#define CP_COMMIT() asm volatile("cp.async.commit_group;" ::: "memory")
__device__ __forceinline__ void ldsm4(uint32_t* r, uint32_t addr) {
    asm volatile("ldmatrix.sync.aligned.m8n8.x4.shared.b16 {%0,%1,%2,%3}, [%4];"
        : "=r"(r[0]), "=r"(r[1]), "=r"(r[2]), "=r"(r[3]) : "r"(addr));
}
__device__ __forceinline__ void mma_f16(float* d, const uint32_t* a, const uint32_t* b) {
    asm volatile("mma.sync.aligned.m16n8k16.row.col.f32.f16.f16.f32 "
        "{%0,%1,%2,%3}, {%4,%5,%6,%7}, {%8,%9}, {%0,%1,%2,%3};"
        : "+f"(d[0]), "+f"(d[1]), "+f"(d[2]), "+f"(d[3])
        : "r"(a[0]), "r"(a[1]), "r"(a[2]), "r"(a[3]), "r"(b[0]), "r"(b[1]));
}
__device__ __forceinline__ float ex2f(float x) {
    float y; asm("ex2.approx.ftz.f32 %0, %1;" : "=f"(y) : "f"(x)); return y;
}
// pack (p0 -> lo16, p1 -> hi16) as fp16x2
__device__ __forceinline__ uint32_t f16x2(float p0, float p1) {
    uint32_t r;
    asm("cvt.rn.f16x2.f32 %0, %1, %2;" : "=r"(r) : "f"(p1), "f"(p0));
    return r;
}
__device__ __forceinline__ void store1h(__half* dst, size_t off, float v0, float v1) {
    *(__half2*)(dst + off) = __half2(__float2half_rn(v0), __float2half_rn(v1));
}
#define SWZ(off) ((off) ^ (((off) >> 3) & 0x70))

// ---------------- repack QKV weights (smem transpose) + rotary table + bias ----------------
#define TBLK_QKV 6144   // 24 heads x (64 ktiles x 4 htiles)
#define ROTB 1024
__global__ void repack_wqkv_rot(const float* __restrict__ WQ, const float* __restrict__ WK,
                                const float* __restrict__ WV, const float* __restrict__ bQ,
                                const float* __restrict__ bK, const float* __restrict__ bV) {
    int b = blockIdx.x;
    int tid = threadIdx.x;
    if (b >= TBLK_QKV + ROTB) {                 // bias
        int idx = (b - TBLK_QKV - ROTB) * 256 + tid;
        if (idx >= NCOLS) return;
        float v;
        if      (idx < 2048) v = bQ[idx];
        else if (idx < 2560) v = bK[idx - 2048];
        else                 v = bV[idx - 2560];
        g_bcat[idx] = v;
        return;
    }
    if (b >= TBLK_QKV) {                        // rotary table
        int idx = (b - TBLK_QKV) * 256 + tid;
        int j = idx & 63, s = idx >> 6;
        double dfreq = pow(10000.0, -(double)j / 64.0);
        float freq = (float)dfreq;
        float angle = (float)s * freq;
        double da = (double)angle;
        g_rcos[idx] = (float)cos(da);
        g_rsin[idx] = (float)sin(da);
        return;
    }
    __shared__ float tile[32][33];
    int H = b >> 8;
    int rem = b & 255;
    int k0 = (rem >> 2) * 32;
    int h0 = (rem & 3) * 32;
    const float* src;
    int nbase;
    if (H < 16)      { src = WQ + (size_t)H * KDIM * DHEAD;        nbase = H * 128; }
    else if (H < 20) { src = WK + (size_t)(H - 16) * KDIM * DHEAD; nbase = 2048 + (H - 16) * 128; }
    else             { src = WV + (size_t)(H - 20) * KDIM * DHEAD; nbase = 2560 + (H - 20) * 128; }
    int c = tid & 31, r0t = tid >> 5;
    #pragma unroll
    for (int p = 0; p < 4; p++) {
        int r = r0t + p * 8;
        tile[r][c] = src[(size_t)(k0 + r) * DHEAD + h0 + c];
    }
    __syncthreads();
    #pragma unroll
    for (int p = 0; p < 4; p++) {
        int rr = r0t + p * 8;
        g_Wthi[(size_t)(nbase + h0 + rr) * KDIM + k0 + c] = __float2half_rn(tile[c][rr]);
    }
}

// W_O transpose: src [2048 nh][2048 m] -> dest [m][nh]; grid (64,64)
__global__ void repack_wo(const float* __restrict__ WO) {
    __shared__ float tile[32][33];
    int n0 = blockIdx.x * 32;
    int m0 = blockIdx.y * 32;
    int tid = threadIdx.x;
    int c = tid & 31, r0t = tid >> 5;
    #pragma unroll
    for (int p = 0; p < 4; p++) {
        int r = r0t + p * 8;
        tile[r][c] = WO[(size_t)(n0 + r) * DMODEL + m0 + c];
    }
    __syncthreads();
    #pragma unroll
    for (int p = 0; p < 4; p++) {
        int rr = r0t + p * 8;
        g_WOthi[(size_t)(m0 + rr) * KDIM + n0 + c] = __float2half_rn(tile[c][rr]);
    }
}

__global__ void conv_f32h(const float* __restrict__ src, __half* __restrict__ dst, int n) {
    int i = blockIdx.x * blockDim.x + threadIdx.x;
    if (i >= n) return;
    dst[i] = __float2half_rn(src[i]);
}

// ---------------- mma.sync fp16 GEMM: A (fp16) x W^T (fp16), 2 CTA/SM ----------------
#define BM 128
#define BN 128
#define BKT 64
#define MATB 16384
#define BUFB (2 * MATB)        // A|B = 32 KB per stage
#define GSMEM (2 * BUFB)       // 64 KB
#define NSTG (KDIM / BKT)      // 32

__device__ __forceinline__ void load_stage(uint32_t bb, int k0, int m0, int n0, int tid,
                                           const __half* Ah, const __half* Bh) {
    #pragma unroll
    for (int i = 0; i < 4; i++) {
        int c = tid + i * 256;
        int r = c >> 3, ch = c & 7;
        uint32_t so = bb + SWZ(r * 128 + ch * 16);
        cp16(so,        Ah + (size_t)(m0 + r) * KDIM + k0 + ch * 8);
        cp16(so + MATB, Bh + (size_t)(n0 + r) * KDIM + k0 + ch * 8);
    }
}

template<int EPI>
__global__ __launch_bounds__(256, 2) void gemm3(
    const __half* __restrict__ Ah, const __half* __restrict__ Bh,
    const float* __restrict__ bias, float* __restrict__ C, int N)
{
    extern __shared__ char sm[];
    const uint32_t smb = smem_u32(sm);
    const int tid = threadIdx.x;
    const int wid = tid >> 5, lid = tid & 31;
    const int m0 = blockIdx.x * BM, n0 = blockIdx.y * BN;
    const int wm = (wid & 1) * 64;
    const int wn = (wid >> 1) * 32;

    float acc[4][4][4];
    #pragma unroll
    for (int i = 0; i < 4; i++)
        #pragma unroll
        for (int j = 0; j < 4; j++)
            #pragma unroll
            for (int k = 0; k < 4; k++) acc[i][j][k] = 0.f;

    const int arow = lid & 15;
    const int asel = (lid >> 4) * 16;
    const int brow = ((lid >> 4) << 3) + (lid & 7);
    const int bsel = ((lid >> 3) & 1) * 16;

    load_stage(smb, 0, m0, n0, tid, Ah, Bh);
    CP_COMMIT();

    for (int s = 0; s < NSTG; s++) {
        if (s + 1 < NSTG) {
            load_stage(smb + ((s + 1) & 1) * BUFB, (s + 1) * BKT, m0, n0, tid, Ah, Bh);
            CP_COMMIT();
            asm volatile("cp.async.wait_group 1;" ::: "memory");
        } else {
            asm volatile("cp.async.wait_group 0;" ::: "memory");
        }
        __syncthreads();

        uint32_t bb = smb + (s & 1) * BUFB;
        #pragma unroll
        for (int kk = 0; kk < 4; kk++) {
            uint32_t ah[4][4];
            #pragma unroll
            for (int ms = 0; ms < 4; ms++) {
                ldsm4(ah[ms], bb + SWZ((wm + ms * 16 + arow) * 128 + kk * 32 + asel));
            }
            uint32_t bh[2][4];
            #pragma unroll
            for (int ns = 0; ns < 2; ns++) {
                ldsm4(bh[ns], bb + MATB + SWZ((wn + ns * 16 + brow) * 128 + kk * 32 + bsel));
            }
            #pragma unroll
            for (int ms = 0; ms < 4; ms++)
                #pragma unroll
                for (int n8 = 0; n8 < 4; n8++)
                    mma_f16(acc[ms][n8], ah[ms], &bh[n8 >> 1][(n8 & 1) * 2]);
        }
        __syncthreads();
    }

    const int erow = lid >> 2, ecol = (lid & 3) * 2;
    #pragma unroll
    for (int ms = 0; ms < 4; ms++) {
        int r0 = m0 + wm + ms * 16 + erow;
        #pragma unroll
        for (int n8 = 0; n8 < 4; n8++) {
            int c = n0 + wn + n8 * 8 + ecol;
            float2 bv = *(const float2*)&bias[c];
            float a00 = acc[ms][n8][0] + bv.x, a01 = acc[ms][n8][1] + bv.y;
            float a10 = acc[ms][n8][2] + bv.x, a11 = acc[ms][n8][3] + bv.y;
            if (EPI == 0) {
                *(float2*)&C[(size_t)r0 * N + c]       = make_float2(a00, a01);
                *(float2*)&C[(size_t)(r0 + 8) * N + c] = make_float2(a10, a11);
            } else {
                if (n0 < 2048) {                       // Q: rotary + fp16
                    int j = (c & 127) >> 1;
                    float c0 = g_rcos[r0 * 64 + j],       s0 = g_rsin[r0 * 64 + j];
                    float c1 = g_rcos[(r0 + 8) * 64 + j], s1 = g_rsin[(r0 + 8) * 64 + j];
                    store1h(g_qh, (size_t)r0 * DMODEL + c,
                            a00 * c0 - a01 * s0, a00 * s0 + a01 * c0);
                    store1h(g_qh, (size_t)(r0 + 8) * DMODEL + c,
                            a10 * c1 - a11 * s1, a10 * s1 + a11 * c1);
                } else if (n0 < 2560) {                // K: rotary + fp16, [kvh][s][dh]
                    int kvh = (c - 2048) >> 7, dh = c & 127, j = dh >> 1;
                    float c0 = g_rcos[r0 * 64 + j],       s0 = g_rsin[r0 * 64 + j];
                    float c1 = g_rcos[(r0 + 8) * 64 + j], s1 = g_rsin[(r0 + 8) * 64 + j];
                    size_t base = ((size_t)kvh * SEQ + r0) * DHEAD + dh;
                    store1h(g_kh, base,
                            a00 * c0 - a01 * s0, a00 * s0 + a01 * c0);
                    store1h(g_kh, base + 8 * DHEAD,
                            a10 * c1 - a11 * s1, a10 * s1 + a11 * c1);
                } else {                               // V: fp16 + transpose [kvh][dh][s]
                    int kvh = (c - 2560) >> 7, dh = c & 127;
                    size_t b0 = ((size_t)kvh * DHEAD + dh) * SEQ;
                    size_t b1 = b0 + SEQ;
                    g_vthi[b0 + r0]     = __float2half_rn(a00);
                    g_vthi[b1 + r0]     = __float2half_rn(a01);
                    g_vthi[b0 + r0 + 8] = __float2half_rn(a10);
                    g_vthi[b1 + r0 + 8] = __float2half_rn(a11);
                }
            }
        }
    }
}

// ---------------- flash attention (all fp16 single; 2 CTA/SM) ----------------
// smem: Q 32KB (2 planes 16KB) | K 2x16KB | V 2x16KB = 96KB
#define SMK 32768
#define SMV 65536
#define ATT_SMEM 98304

__device__ __forceinline__ void load_kv_stage(uint32_t smb, int buf, int kv0, int tid,
                                              const __half* kh, const __half* vhi) {
    #pragma unroll
    for (int sb = 0; sb < 2; sb++) {
        #pragma unroll
        for (int i = 0; i < 2; i++) {
            int c = tid + i * 256;
            int r = c >> 3, ch = c & 7;
            cp16(smb + SMK + buf * 16384 + sb * 8192 + SWZ(r * 128 + ch * 16),
                 kh + (size_t)(kv0 + r) * DHEAD + sb * 64 + ch * 8);
        }
    }
    #pragma unroll
    for (int i = 0; i < 4; i++) {
        int c = tid + i * 256;
        int d = c >> 3, ch = c & 7;
        cp16(smb + SMV + buf * 16384 + SWZ(d * 128 + ch * 16),
             vhi + (size_t)d * SEQ + kv0 + ch * 8);
    }
}

__global__ __launch_bounds__(256, 2) void attn_mma() {
    extern __shared__ char sm[];
    const uint32_t smb = smem_u32(sm);
    const int tid = threadIdx.x;
    const int wid = tid >> 5, lid = tid & 31;
    const int qb = (int)(gridDim.x - 1) - (int)blockIdx.x;
    const int h = blockIdx.y;
    const int kvh = h >> 2;
    const int q0 = qb * 128;
    const int nkv = 2 * qb + 2;
    const int w16 = wid * 16;

    const int arow = lid & 15;
    const int asel = (lid >> 4) * 16;
    const int brow = ((lid >> 4) << 3) + (lid & 7);
    const int bsel = ((lid >> 3) & 1) * 16;

    const __half* kh  = g_kh + (size_t)kvh * SEQ * DHEAD;
    const __half* vhi = g_vthi + (size_t)kvh * DHEAD * SEQ;

    // prologue: Q tile (2 planes) + KV stage 0
    #pragma unroll
    for (int b = 0; b < 2; b++) {
        #pragma unroll
        for (int i = 0; i < 4; i++) {
            int c = tid + i * 256;
            int r = c >> 3, ch = c & 7;
            cp16(smb + b * 16384 + SWZ(r * 128 + ch * 16),
                 g_qh + (size_t)(q0 + r) * DMODEL + h * DHEAD + b * 64 + ch * 8);
        }
    }
    load_kv_stage(smb, 0, 0, tid, kh, vhi);
    CP_COMMIT();

    float oacc[16][4];
    #pragma unroll
    for (int i = 0; i < 16; i++)
        #pragma unroll
        for (int j = 0; j < 4; j++) oacc[i][j] = 0.f;
    float m2[2] = {-1e30f, -1e30f};
    float l2[2] = {0.f, 0.f};
    const float KE = (float)(1.4426950408889634 / 11.313708498984761);

    for (int kb = 0; kb < nkv; kb++) {
        if (kb + 1 < nkv) {
            load_kv_stage(smb, (kb + 1) & 1, (kb + 1) * 64, tid, kh, vhi);
            CP_COMMIT();
            asm volatile("cp.async.wait_group 1;" ::: "memory");
        } else {
            asm volatile("cp.async.wait_group 0;" ::: "memory");
        }
        __syncthreads();

        const uint32_t kbase = smb + SMK + (kb & 1) * 16384;
        const uint32_t vbase = smb + SMV + (kb & 1) * 16384;

        // ---- S = Q K^T (fp16 single) ----
        float sacc[8][4];
        #pragma unroll
        for (int i = 0; i < 8; i++)
            #pragma unroll
            for (int j = 0; j < 4; j++) sacc[i][j] = 0.f;

        #pragma unroll
        for (int kk = 0; kk < 8; kk++) {
            int b = kk >> 2, koff = (kk & 3) * 32;
            uint32_t qh[4];
            ldsm4(qh, smb + b * 16384 + SWZ((w16 + arow) * 128 + koff + asel));
            #pragma unroll
            for (int ns = 0; ns < 4; ns++) {
                uint32_t bk[4];
                ldsm4(bk, kbase + b * 8192 + SWZ((ns * 16 + brow) * 128 + koff + bsel));
                mma_f16(sacc[2 * ns],     qh, bk);
                mma_f16(sacc[2 * ns + 1], qh, bk + 2);
            }
        }

        // ---- online softmax ----
        const int kv0 = kb * 64;
        const bool dodiag = (kb >= nkv - 2);
        #pragma unroll
        for (int g = 0; g < 2; g++) {
            int grow = q0 + w16 + (lid >> 2) + g * 8;
            if (dodiag) {
                #pragma unroll
                for (int n8 = 0; n8 < 8; n8++) {
                    int col = kv0 + n8 * 8 + (lid & 3) * 2;
                    if (col > grow)     sacc[n8][2 * g]     = -1e30f;
                    if (col + 1 > grow) sacc[n8][2 * g + 1] = -1e30f;
                }
            }
            float mt = -1e30f;
            #pragma unroll
            for (int n8 = 0; n8 < 8; n8++)
                mt = fmaxf(mt, fmaxf(sacc[n8][2 * g], sacc[n8][2 * g + 1]));
            mt = fmaxf(mt, __shfl_xor_sync(0xffffffffu, mt, 1));
            mt = fmaxf(mt, __shfl_xor_sync(0xffffffffu, mt, 2));
            float mnew = fmaxf(m2[g], mt);
            float alpha = ex2f((m2[g] - mnew) * KE);
            float ls = 0.f;
            #pragma unroll
            for (int n8 = 0; n8 < 8; n8++) {
                float p0 = ex2f((sacc[n8][2 * g]     - mnew) * KE);
                float p1 = ex2f((sacc[n8][2 * g + 1] - mnew) * KE);
                sacc[n8][2 * g] = p0; sacc[n8][2 * g + 1] = p1;
                ls += p0 + p1;
            }
            ls += __shfl_xor_sync(0xffffffffu, ls, 1);
            ls += __shfl_xor_sync(0xffffffffu, ls, 2);
            l2[g] = l2[g] * alpha + ls;
            m2[g] = mnew;
            #pragma unroll
            for (int t = 0; t < 16; t++) {
                oacc[t][2 * g]     *= alpha;
                oacc[t][2 * g + 1] *= alpha;
            }
        }

        // ---- O += P V (fp16 single) ----
        #pragma unroll
        for (int t = 0; t < 4; t++) {
            uint32_t pa[4];
            pa[0] = f16x2(sacc[2 * t][0],     sacc[2 * t][1]);
            pa[1] = f16x2(sacc[2 * t][2],     sacc[2 * t][3]);
            pa[2] = f16x2(sacc[2 * t + 1][0], sacc[2 * t + 1][1]);
            pa[3] = f16x2(sacc[2 * t + 1][2], sacc[2 * t + 1][3]);
            #pragma unroll
            for (int ns = 0; ns < 8; ns++) {
                uint32_t vh[4];
                ldsm4(vh, vbase + SWZ((ns * 16 + brow) * 128 + t * 32 + bsel));
                mma_f16(oacc[2 * ns],     pa, vh);
                mma_f16(oacc[2 * ns + 1], pa, vh + 2);
            }
        }
        __syncthreads();
    }

    // ---- epilogue: z as fp16 single ----
    float inv0 = 1.f / l2[0], inv1 = 1.f / l2[1];
    int r0 = q0 + w16 + (lid >> 2);
    int cb = h * DHEAD + (lid & 3) * 2;
    #pragma unroll
    for (int n8 = 0; n8 < 16; n8++) {
        int col = cb + n8 * 8;
        store1h(g_zh, (size_t)r0 * DMODEL + col,
                oacc[n8][0] * inv0, oacc[n8][1] * inv0);
        store1h(g_zh, (size_t)(r0 + 8) * DMODEL + col,
                oacc[n8][2] * inv1, oacc[n8][3] * inv1);
    }
}

// ---------------- launcher ----------------
extern "C" void kernel_launch(void* const* d_in, const int* in_sizes, int n_in,
                              void* d_out, int out_size) {
    const float* x  = (const float*)d_in[0];
    const float* WQ = (const float*)d_in[1];
    const float* WK = (const float*)d_in[2];
    const float* WV = (const float*)d_in[3];
    const float* WO = (const float*)d_in[4];
    const float* bQ = (const float*)d_in[5];
    const float* bK = (const float*)d_in[6];
    const float* bV = (const float*)d_in[7];
    const float* bO = (const float*)d_in[8];
    float* out = (float*)d_out;

    float* bcat;
    __half *xh, *zh, *Wthi, *WOthi;
    cudaGetSymbolAddress((void**)&bcat,  g_bcat);
    cudaGetSymbolAddress((void**)&xh,    g_xh);
    cudaGetSymbolAddress((void**)&zh,    g_zh);
    cudaGetSymbolAddress((void**)&Wthi,  g_Wthi);
    cudaGetSymbolAddress((void**)&WOthi, g_WOthi);

    cudaFuncSetAttribute(gemm3<0>, cudaFuncAttributeMaxDynamicSharedMemorySize, GSMEM);
    cudaFuncSetAttribute(gemm3<1>, cudaFuncAttributeMaxDynamicSharedMemorySize, GSMEM);
    cudaFuncSetAttribute(attn_mma, cudaFuncAttributeMaxDynamicSharedMemorySize, ATT_SMEM);

    // 1) weight repacks (coalesced transposes) + rotary table + bias + input convert
    repack_wqkv_rot<<<TBLK_QKV + ROTB + 12, 256>>>(WQ, WK, WV, bQ, bK, bV);
    {
        dim3 grid(64, 64);
        repack_wo<<<grid, 256>>>(WO);
    }
    conv_f32h<<<(SEQ * DMODEL + 255) / 256, 256>>>(x, xh, SEQ * DMODEL);

    // 2) QKV projection + fused bias/rotary/layout epilogue
    {
        dim3 grid(SEQ / BM, NCOLS / BN);
        gemm3<1><<<grid, 256, GSMEM>>>(xh, Wthi, bcat, nullptr, NCOLS);
    }
    // 3) causal flash attention -> zh
    {
        dim3 grid(SEQ / 128, NH);
        attn_mma<<<grid, 256, ATT_SMEM>>>();
    }
    // 4) O-projection
    {
        dim3 grid(SEQ / BM, DMODEL / BN);
        gemm3<0><<<grid, 256, GSMEM>>>(zh, WOthi, bO, out, DMODEL);
    }
}

// round 11
// speedup vs baseline: 2.6092x; 1.1696x over previous
#include <cuda_runtime.h>
#include <cuda_fp16.h>
#include <math.h>
#include <stdint.h>

#define SEQ     4096
#define DMODEL  2048
#define DHEAD   128
#define NH      16
#define NKV     4
#define NCOLS   3072
#define KDIM    2048

// ---------------- scratch ----------------
__device__ __align__(256) float g_bcat[NCOLS];
__device__ __align__(256) __half g_xh[SEQ * DMODEL];       // x fp16
__device__ __align__(256) __half g_zh[SEQ * DMODEL];       // z fp16
__device__ __align__(256) __half g_Wthi[NCOLS * KDIM];     // QKV W^T fp16
__device__ __align__(256) __half g_WOthi[DMODEL * KDIM];   // W_O^T fp16
__device__ __align__(256) __half g_qh[SEQ * DMODEL];       // Q fp16 (post-rotary)
__device__ __align__(256) __half g_kh[NKV * SEQ * DHEAD];  // K fp16 (post-rotary)
__device__ __align__(256) __half g_vthi[NKV * DHEAD * SEQ];// V^T fp16
__device__ __align__(256) float g_rcos[SEQ * 64];
__device__ __align__(256) float g_rsin[SEQ * 64];

// ---------------- helpers ----------------
__device__ __forceinline__ uint32_t smem_u32(const void* p) {
    uint32_t a;
    asm("{ .reg .u64 t; cvta.to.shared.u64 t, %1; cvt.u32.u64 %0, t; }" : "=r"(a) : "l"(p));
    return a;
}
__device__ __forceinline__ void cp16(uint32_t s, const void* g) {
    asm volatile("cp.async.cg.shared.global [%0], [%1], 16;" :: "r"(s), "l"(g));
}
#define CP_COMMIT() asm volatile("cp.async.commit_group;" ::: "memory")
__device__ __forceinline__ void ldsm4(uint32_t* r, uint32_t addr) {
    asm volatile("ldmatrix.sync.aligned.m8n8.x4.shared.b16 {%0,%1,%2,%3}, [%4];"
        : "=r"(r[0]), "=r"(r[1]), "=r"(r[2]), "=r"(r[3]) : "r"(addr));
}
__device__ __forceinline__ void mma_f16(float* d, const uint32_t* a, const uint32_t* b) {
    asm volatile("mma.sync.aligned.m16n8k16.row.col.f32.f16.f16.f32 "
        "{%0,%1,%2,%3}, {%4,%5,%6,%7}, {%8,%9}, {%0,%1,%2,%3};"
        : "+f"(d[0]), "+f"(d[1]), "+f"(d[2]), "+f"(d[3])
        : "r"(a[0]), "r"(a[1]), "r"(a[2]), "r"(a[3]), "r"(b[0]), "r"(b[1]));
}
__device__ __forceinline__ float ex2f(float x) {
    float y; asm("ex2.approx.ftz.f32 %0, %1;" : "=f"(y) : "f"(x)); return y;
}
__device__ __forceinline__ uint32_t f16x2(float p0, float p1) {
    uint32_t r;
    asm("cvt.rn.f16x2.f32 %0, %1, %2;" : "=r"(r) : "f"(p1), "f"(p0));
    return r;
}
__device__ __forceinline__ void store1h(__half* dst, size_t off, float v0, float v1) {
    *(__half2*)(dst + off) = __half2(__float2half_rn(v0), __float2half_rn(v1));
}
#define SWZ(off) ((off) ^ (((off) >> 3) & 0x70))

// ---------------- mono prep kernel ----------------
// [0,6144): QKV W transpose  [6144,7168): rotary table  [7168,7180): bias
// [7180,11276): W_O transpose  [11276,15372): x fp32->fp16 convert
#define PB_QKV   6144
#define PB_ROT   (PB_QKV + 1024)
#define PB_BIAS  (PB_ROT + 12)
#define PB_WO    (PB_BIAS + 4096)
#define PB_CONV  (PB_WO + 4096)
__global__ void prep_all(const float* __restrict__ x,
                         const float* __restrict__ WQ, const float* __restrict__ WK,
                         const float* __restrict__ WV, const float* __restrict__ WO,
                         const float* __restrict__ bQ, const float* __restrict__ bK,
                         const float* __restrict__ bV) {
    int b = blockIdx.x;
    int tid = threadIdx.x;
    if (b < PB_QKV) {                               // QKV W transpose
        __shared__ float tile[32][33];
        int H = b >> 8;
        int rem = b & 255;
        int k0 = (rem >> 2) * 32;
        int h0 = (rem & 3) * 32;
        const float* src;
        int nbase;
        if (H < 16)      { src = WQ + (size_t)H * KDIM * DHEAD;        nbase = H * 128; }
        else if (H < 20) { src = WK + (size_t)(H - 16) * KDIM * DHEAD; nbase = 2048 + (H - 16) * 128; }
        else             { src = WV + (size_t)(H - 20) * KDIM * DHEAD; nbase = 2560 + (H - 20) * 128; }
        int c = tid & 31, r0t = tid >> 5;
        #pragma unroll
        for (int p = 0; p < 4; p++) {
            int r = r0t + p * 8;
            tile[r][c] = src[(size_t)(k0 + r) * DHEAD + h0 + c];
        }
        __syncthreads();
        #pragma unroll
        for (int p = 0; p < 4; p++) {
            int rr = r0t + p * 8;
            g_Wthi[(size_t)(nbase + h0 + rr) * KDIM + k0 + c] = __float2half_rn(tile[c][rr]);
        }
        return;
    }
    if (b < PB_ROT) {                               // rotary table
        int idx = (b - PB_QKV) * 256 + tid;
        int j = idx & 63, s = idx >> 6;
        double dfreq = pow(10000.0, -(double)j / 64.0);
        float freq = (float)dfreq;
        float angle = (float)s * freq;
        double da = (double)angle;
        g_rcos[idx] = (float)cos(da);
        g_rsin[idx] = (float)sin(da);
        return;
    }
    if (b < PB_BIAS) {                              // bias concat
        int idx = (b - PB_ROT) * 256 + tid;
        if (idx >= NCOLS) return;
        float v;
        if      (idx < 2048) v = bQ[idx];
        else if (idx < 2560) v = bK[idx - 2048];
        else                 v = bV[idx - 2560];
        g_bcat[idx] = v;
        return;
    }
    if (b < PB_WO) {                                // W_O transpose
        __shared__ float tile[32][33];
        int i = b - PB_BIAS;
        int n0 = (i >> 6) * 32;
        int m0 = (i & 63) * 32;
        int c = tid & 31, r0t = tid >> 5;
        #pragma unroll
        for (int p = 0; p < 4; p++) {
            int r = r0t + p * 8;
            tile[r][c] = WO[(size_t)(n0 + r) * DMODEL + m0 + c];
        }
        __syncthreads();
        #pragma unroll
        for (int p = 0; p < 4; p++) {
            int rr = r0t + p * 8;
            g_WOthi[(size_t)(m0 + rr) * KDIM + n0 + c] = __float2half_rn(tile[c][rr]);
        }
        return;
    }
    {                                               // x convert, 8 elems/thread
        int base = (b - PB_WO) * 2048 + tid * 8;
        float4 v0 = *(const float4*)(x + base);
        float4 v1 = *(const float4*)(x + base + 4);
        __half h[8];
        h[0] = __float2half_rn(v0.x); h[1] = __float2half_rn(v0.y);
        h[2] = __float2half_rn(v0.z); h[3] = __float2half_rn(v0.w);
        h[4] = __float2half_rn(v1.x); h[5] = __float2half_rn(v1.y);
        h[6] = __float2half_rn(v1.z); h[7] = __float2half_rn(v1.w);
        *(uint4*)(g_xh + base) = *(uint4*)h;
    }
}

// ---------------- mma.sync fp16 GEMM: BM=128, BN=256, warp 64x64, 1 CTA/SM ----------------
#define BM 128
#define BN 256
#define BKT 64
#define MATA 16384             // A: 128 x 128B
#define MATBB 32768            // B: 256 x 128B
#define BUFB (MATA + MATBB)    // 48 KB per stage
#define GSMEM (2 * BUFB)       // 96 KB
#define NSTG (KDIM / BKT)      // 32

__device__ __forceinline__ void load_stage(uint32_t bb, int k0, int m0, int n0, int tid,
                                           const __half* Ah, const __half* Bh) {
    #pragma unroll
    for (int i = 0; i < 4; i++) {
        int c = tid + i * 256;
        int r = c >> 3, ch = c & 7;
        cp16(bb + SWZ(r * 128 + ch * 16), Ah + (size_t)(m0 + r) * KDIM + k0 + ch * 8);
    }
    #pragma unroll
    for (int i = 0; i < 8; i++) {
        int c = tid + i * 256;
        int r = c >> 3, ch = c & 7;
        cp16(bb + MATA + SWZ(r * 128 + ch * 16), Bh + (size_t)(n0 + r) * KDIM + k0 + ch * 8);
    }
}

template<int EPI>
__global__ __launch_bounds__(256, 1) void gemm3(
    const __half* __restrict__ Ah, const __half* __restrict__ Bh,
    const float* __restrict__ bias, float* __restrict__ C, int N)
{
    extern __shared__ char sm[];
    const uint32_t smb = smem_u32(sm);
    const int tid = threadIdx.x;
    const int wid = tid >> 5, lid = tid & 31;
    const int m0 = blockIdx.x * BM, n0 = blockIdx.y * BN;
    const int wm = (wid & 1) * 64;
    const int wn = (wid >> 1) * 64;

    float acc[4][8][4];
    #pragma unroll
    for (int i = 0; i < 4; i++)
        #pragma unroll
        for (int j = 0; j < 8; j++)
            #pragma unroll
            for (int k = 0; k < 4; k++) acc[i][j][k] = 0.f;

    const int arow = lid & 15;
    const int asel = (lid >> 4) * 16;
    const int brow = ((lid >> 4) << 3) + (lid & 7);
    const int bsel = ((lid >> 3) & 1) * 16;

    load_stage(smb, 0, m0, n0, tid, Ah, Bh);
    CP_COMMIT();

    for (int s = 0; s < NSTG; s++) {
        if (s + 1 < NSTG) {
            load_stage(smb + ((s + 1) & 1) * BUFB, (s + 1) * BKT, m0, n0, tid, Ah, Bh);
            CP_COMMIT();
            asm volatile("cp.async.wait_group 1;" ::: "memory");
        } else {
            asm volatile("cp.async.wait_group 0;" ::: "memory");
        }
        __syncthreads();

        uint32_t bb = smb + (s & 1) * BUFB;
        #pragma unroll
        for (int kk = 0; kk < 4; kk++) {
            uint32_t ah[4][4];
            #pragma unroll
            for (int ms = 0; ms < 4; ms++)
                ldsm4(ah[ms], bb + SWZ((wm + ms * 16 + arow) * 128 + kk * 32 + asel));
            uint32_t bh[4][4];
            #pragma unroll
            for (int ns = 0; ns < 4; ns++)
                ldsm4(bh[ns], bb + MATA + SWZ((wn + ns * 16 + brow) * 128 + kk * 32 + bsel));
            #pragma unroll
            for (int ms = 0; ms < 4; ms++)
                #pragma unroll
                for (int n8 = 0; n8 < 8; n8++)
                    mma_f16(acc[ms][n8], ah[ms], &bh[n8 >> 1][(n8 & 1) * 2]);
        }
        __syncthreads();
    }

    const int erow = lid >> 2, ecol = (lid & 3) * 2;
    #pragma unroll
    for (int ms = 0; ms < 4; ms++) {
        int r0 = m0 + wm + ms * 16 + erow;
        #pragma unroll
        for (int n8 = 0; n8 < 8; n8++) {
            int c = n0 + wn + n8 * 8 + ecol;
            float2 bv = *(const float2*)&bias[c];
            float a00 = acc[ms][n8][0] + bv.x, a01 = acc[ms][n8][1] + bv.y;
            float a10 = acc[ms][n8][2] + bv.x, a11 = acc[ms][n8][3] + bv.y;
            if (EPI == 0) {
                *(float2*)&C[(size_t)r0 * N + c]       = make_float2(a00, a01);
                *(float2*)&C[(size_t)(r0 + 8) * N + c] = make_float2(a10, a11);
            } else {
                if (c < 2048) {                        // Q: rotary + fp16
                    int j = (c & 127) >> 1;
                    float c0 = g_rcos[r0 * 64 + j],       s0 = g_rsin[r0 * 64 + j];
                    float c1 = g_rcos[(r0 + 8) * 64 + j], s1 = g_rsin[(r0 + 8) * 64 + j];
                    store1h(g_qh, (size_t)r0 * DMODEL + c,
                            a00 * c0 - a01 * s0, a00 * s0 + a01 * c0);
                    store1h(g_qh, (size_t)(r0 + 8) * DMODEL + c,
                            a10 * c1 - a11 * s1, a10 * s1 + a11 * c1);
                } else if (c < 2560) {                 // K: rotary + fp16, [kvh][s][dh]
                    int kvh = (c - 2048) >> 7, dh = c & 127, j = dh >> 1;
                    float c0 = g_rcos[r0 * 64 + j],       s0 = g_rsin[r0 * 64 + j];
                    float c1 = g_rcos[(r0 + 8) * 64 + j], s1 = g_rsin[(r0 + 8) * 64 + j];
                    size_t base = ((size_t)kvh * SEQ + r0) * DHEAD + dh;
                    store1h(g_kh, base,
                            a00 * c0 - a01 * s0, a00 * s0 + a01 * c0);
                    store1h(g_kh, base + 8 * DHEAD,
                            a10 * c1 - a11 * s1, a10 * s1 + a11 * c1);
                } else {                               // V: fp16 + transpose [kvh][dh][s]
                    int kvh = (c - 2560) >> 7, dh = c & 127;
                    size_t b0 = ((size_t)kvh * DHEAD + dh) * SEQ;
                    size_t b1 = b0 + SEQ;
                    g_vthi[b0 + r0]     = __float2half_rn(a00);
                    g_vthi[b1 + r0]     = __float2half_rn(a01);
                    g_vthi[b0 + r0 + 8] = __float2half_rn(a10);
                    g_vthi[b1 + r0 + 8] = __float2half_rn(a11);
                }
            }
        }
    }
}

// ---------------- flash attention (fp16; BKV=128; 1 CTA/SM) ----------------
// smem: Q 32KB (2 planes 16KB) | K 2 bufs x 32KB | V 2 bufs x 32KB = 160KB
#define SMK 32768
#define SMV 98304
#define ATT_SMEM 163840

__device__ __forceinline__ void load_kv_stage(uint32_t smb, int buf, int kv0, int tid,
                                              const __half* kh, const __half* vhi) {
    // K: 2 sub-blocks [128 rows][64 dh = 128B]
    #pragma unroll
    for (int sb = 0; sb < 2; sb++) {
        #pragma unroll
        for (int i = 0; i < 4; i++) {
            int c = tid + i * 256;
            int r = c >> 3, ch = c & 7;
            cp16(smb + SMK + buf * 32768 + sb * 16384 + SWZ(r * 128 + ch * 16),
                 kh + (size_t)(kv0 + r) * DHEAD + sb * 64 + ch * 8);
        }
    }
    // V^T: 2 sub-blocks [128 dh][64 kv = 128B]
    #pragma unroll
    for (int sb = 0; sb < 2; sb++) {
        #pragma unroll
        for (int i = 0; i < 4; i++) {
            int c = tid + i * 256;
            int d = c >> 3, ch = c & 7;
            cp16(smb + SMV + buf * 32768 + sb * 16384 + SWZ(d * 128 + ch * 16),
                 vhi + (size_t)d * SEQ + kv0 + sb * 64 + ch * 8);
        }
    }
}

__global__ __launch_bounds__(256, 1) void attn_mma() {
    extern __shared__ char sm[];
    const uint32_t smb = smem_u32(sm);
    const int tid = threadIdx.x;
    const int wid = tid >> 5, lid = tid & 31;
    const int qb = (int)(gridDim.x - 1) - (int)blockIdx.x;
    const int h = blockIdx.y;
    const int kvh = h >> 2;
    const int q0 = qb * 128;
    const int nkv = qb + 1;          // 128-wide kv blocks
    const int w16 = wid * 16;

    const int arow = lid & 15;
    const int asel = (lid >> 4) * 16;
    const int brow = ((lid >> 4) << 3) + (lid & 7);
    const int bsel = ((lid >> 3) & 1) * 16;

    const __half* kh  = g_kh + (size_t)kvh * SEQ * DHEAD;
    const __half* vhi = g_vthi + (size_t)kvh * DHEAD * SEQ;

    // prologue: Q tile (2 planes) + KV stage 0
    #pragma unroll
    for (int b = 0; b < 2; b++) {
        #pragma unroll
        for (int i = 0; i < 4; i++) {
            int c = tid + i * 256;
            int r = c >> 3, ch = c & 7;
            cp16(smb + b * 16384 + SWZ(r * 128 + ch * 16),
                 g_qh + (size_t)(q0 + r) * DMODEL + h * DHEAD + b * 64 + ch * 8);
        }
    }
    load_kv_stage(smb, 0, 0, tid, kh, vhi);
    CP_COMMIT();

    float oacc[16][4];
    #pragma unroll
    for (int i = 0; i < 16; i++)
        #pragma unroll
        for (int j = 0; j < 4; j++) oacc[i][j] = 0.f;
    float m2[2] = {-1e30f, -1e30f};
    float l2[2] = {0.f, 0.f};
    const float KE = (float)(1.4426950408889634 / 11.313708498984761);

    for (int kb = 0; kb < nkv; kb++) {
        if (kb + 1 < nkv) {
            load_kv_stage(smb, (kb + 1) & 1, (kb + 1) * 128, tid, kh, vhi);
            CP_COMMIT();
            asm volatile("cp.async.wait_group 1;" ::: "memory");
        } else {
            asm volatile("cp.async.wait_group 0;" ::: "memory");
        }
        __syncthreads();

        const uint32_t kbase = smb + SMK + (kb & 1) * 32768;
        const uint32_t vbase = smb + SMV + (kb & 1) * 32768;

        // ---- S = Q K^T over 128 kv cols ----
        float sacc[16][4];
        #pragma unroll
        for (int i = 0; i < 16; i++)
            #pragma unroll
            for (int j = 0; j < 4; j++) sacc[i][j] = 0.f;

        #pragma unroll
        for (int kk = 0; kk < 8; kk++) {
            int sb = kk >> 2, koff = (kk & 3) * 32;
            uint32_t qh[4];
            ldsm4(qh, smb + sb * 16384 + SWZ((w16 + arow) * 128 + koff + asel));
            #pragma unroll
            for (int ns = 0; ns < 8; ns++) {
                uint32_t bk[4];
                ldsm4(bk, kbase + sb * 16384 + SWZ((ns * 16 + brow) * 128 + koff + bsel));
                mma_f16(sacc[2 * ns],     qh, bk);
                mma_f16(sacc[2 * ns + 1], qh, bk + 2);
            }
        }

        // ---- online softmax (128 cols) ----
        const int kv0 = kb * 128;
        const bool dodiag = (kb == nkv - 1);
        #pragma unroll
        for (int g = 0; g < 2; g++) {
            int grow = q0 + w16 + (lid >> 2) + g * 8;
            if (dodiag) {
                #pragma unroll
                for (int n8 = 0; n8 < 16; n8++) {
                    int col = kv0 + n8 * 8 + (lid & 3) * 2;
                    if (col > grow)     sacc[n8][2 * g]     = -1e30f;
                    if (col + 1 > grow) sacc[n8][2 * g + 1] = -1e30f;
                }
            }
            float mt = -1e30f;
            #pragma unroll
            for (int n8 = 0; n8 < 16; n8++)
                mt = fmaxf(mt, fmaxf(sacc[n8][2 * g], sacc[n8][2 * g + 1]));
            mt = fmaxf(mt, __shfl_xor_sync(0xffffffffu, mt, 1));
            mt = fmaxf(mt, __shfl_xor_sync(0xffffffffu, mt, 2));
            float mnew = fmaxf(m2[g], mt);
            float alpha = ex2f((m2[g] - mnew) * KE);
            float ls = 0.f;
            #pragma unroll
            for (int n8 = 0; n8 < 16; n8++) {
                float p0 = ex2f((sacc[n8][2 * g]     - mnew) * KE);
                float p1 = ex2f((sacc[n8][2 * g + 1] - mnew) * KE);
                sacc[n8][2 * g] = p0; sacc[n8][2 * g + 1] = p1;
                ls += p0 + p1;
            }
            ls += __shfl_xor_sync(0xffffffffu, ls, 1);
            ls += __shfl_xor_sync(0xffffffffu, ls, 2);
            l2[g] = l2[g] * alpha + ls;
            m2[g] = mnew;
            #pragma unroll
            for (int t = 0; t < 16; t++) {
                oacc[t][2 * g]     *= alpha;
                oacc[t][2 * g + 1] *= alpha;
            }
        }

        // ---- O += P V (8 k16 chunks over 128 kv) ----
        #pragma unroll
        for (int t = 0; t < 8; t++) {
            uint32_t pa[4];
            pa[0] = f16x2(sacc[2 * t][0],     sacc[2 * t][1]);
            pa[1] = f16x2(sacc[2 * t][2],     sacc[2 * t][3]);
            pa[2] = f16x2(sacc[2 * t + 1][0], sacc[2 * t + 1][1]);
            pa[3] = f16x2(sacc[2 * t + 1][2], sacc[2 * t + 1][3]);
            int sb = t >> 2, koff = (t & 3) * 32;
            #pragma unroll
            for (int ns = 0; ns < 8; ns++) {
                uint32_t vh[4];
                ldsm4(vh, vbase + sb * 16384 + SWZ((ns * 16 + brow) * 128 + koff + bsel));
                mma_f16(oacc[2 * ns],     pa, vh);
                mma_f16(oacc[2 * ns + 1], pa, vh + 2);
            }
        }
        __syncthreads();
    }

    // ---- epilogue: z as fp16 ----
    float inv0 = 1.f / l2[0], inv1 = 1.f / l2[1];
    int r0 = q0 + w16 + (lid >> 2);
    int cb = h * DHEAD + (lid & 3) * 2;
    #pragma unroll
    for (int n8 = 0; n8 < 16; n8++) {
        int col = cb + n8 * 8;
        store1h(g_zh, (size_t)r0 * DMODEL + col,
                oacc[n8][0] * inv0, oacc[n8][1] * inv0);
        store1h(g_zh, (size_t)(r0 + 8) * DMODEL + col,
                oacc[n8][2] * inv1, oacc[n8][3] * inv1);
    }
}

// ---------------- launcher ----------------
extern "C" void kernel_launch(void* const* d_in, const int* in_sizes, int n_in,
                              void* d_out, int out_size) {
    const float* x  = (const float*)d_in[0];
    const float* WQ = (const float*)d_in[1];
    const float* WK = (const float*)d_in[2];
    const float* WV = (const float*)d_in[3];
    const float* WO = (const float*)d_in[4];
    const float* bQ = (const float*)d_in[5];
    const float* bK = (const float*)d_in[6];
    const float* bV = (const float*)d_in[7];
    const float* bO = (const float*)d_in[8];
    float* out = (float*)d_out;

    float* bcat;
    __half *xh, *zh, *Wthi, *WOthi;
    cudaGetSymbolAddress((void**)&bcat,  g_bcat);
    cudaGetSymbolAddress((void**)&xh,    g_xh);
    cudaGetSymbolAddress((void**)&zh,    g_zh);
    cudaGetSymbolAddress((void**)&Wthi,  g_Wthi);
    cudaGetSymbolAddress((void**)&WOthi, g_WOthi);

    cudaFuncSetAttribute(gemm3<0>, cudaFuncAttributeMaxDynamicSharedMemorySize, GSMEM);
    cudaFuncSetAttribute(gemm3<1>, cudaFuncAttributeMaxDynamicSharedMemorySize, GSMEM);
    cudaFuncSetAttribute(attn_mma, cudaFuncAttributeMaxDynamicSharedMemorySize, ATT_SMEM);

    // 1) all prep in one launch
    prep_all<<<PB_CONV, 256>>>(x, WQ, WK, WV, WO, bQ, bK, bV);

    // 2) QKV projection + fused bias/rotary/layout epilogue
    {
        dim3 grid(SEQ / BM, NCOLS / BN);
        gemm3<1><<<grid, 256, GSMEM>>>(xh, Wthi, bcat, nullptr, NCOLS);
    }
    // 3) causal flash attention -> zh
    {
        dim3 grid(SEQ / 128, NH);
        attn_mma<<<grid, 256, ATT_SMEM>>>();
    }
    // 4) O-projection
    {
        dim3 grid(SEQ / BM, DMODEL / BN);
        gemm3<0><<<grid, 256, GSMEM>>>(zh, WOthi, bO, out, DMODEL);
    }
}